// round 10
// baseline (speedup 1.0000x reference)
#include <cuda_runtime.h>
#include <math.h>
#include <stdint.h>

#define NB 32
#define NC 256
#define NH 64
#define NW 64
#define NHW 4096
#define NCHW (NC*NHW)
#define EPSV 1e-5f

// Scratch (allocation-free rule: __device__ globals)
__device__ float g_pooled[NB*NC];
__device__ int   g_idx[NB];
__device__ float g_feat[(size_t)NB*NCHW];   // tf32-rounded feature scratch
__device__ float g_wt[4][NC*NC];            // tf32-rounded weights: e0_pw,e1_pw,e2_pw,e2_k

__device__ __forceinline__ uint32_t f2tf32(float f) {
    uint32_t r;
    asm("cvt.rna.tf32.f32 %0, %1;" : "=r"(r) : "f"(f));
    return r;
}
__device__ __forceinline__ float f2tf32f(float f) { return __uint_as_float(f2tf32(f)); }

// exact GELU: z * Phi(z) = 0.5 z (1 + erf(z/sqrt(2)))
__device__ __forceinline__ float gelu_exact(float z) {
    return 0.5f * z * (1.0f + erff(z * 0.7071067811865475f));
}

// ---------------------------------------------------------------------------
// 1) Fused: global average pool (blocks 0..8191) + weight pre-convert (8192..9215)
// ---------------------------------------------------------------------------
__global__ void pool_prep_kernel(const float* __restrict__ x,
                                 const float* __restrict__ w0, const float* __restrict__ w1,
                                 const float* __restrict__ w2, const float* __restrict__ k2) {
    if (blockIdx.x < NB*NC) {
        int bc = blockIdx.x;
        const float4* p = reinterpret_cast<const float4*>(x + (size_t)bc * NHW);
        float s = 0.f;
        for (int i = threadIdx.x; i < NHW/4; i += 256) {
            float4 v = p[i];
            s += (v.x + v.y) + (v.z + v.w);
        }
        __shared__ float red[8];
        #pragma unroll
        for (int o = 16; o > 0; o >>= 1) s += __shfl_down_sync(0xffffffffu, s, o);
        if ((threadIdx.x & 31) == 0) red[threadIdx.x >> 5] = s;
        __syncthreads();
        if (threadIdx.x < 8) {
            float t = red[threadIdx.x];
            #pragma unroll
            for (int o = 4; o > 0; o >>= 1) t += __shfl_down_sync(0xffu, t, o);
            if (threadIdx.x == 0) g_pooled[bc] = t * (1.0f / NHW);
        }
    } else {
        int i = (blockIdx.x - NB*NC) * 256 + threadIdx.x;
        int m = i >> 16;
        int o = i & 0xFFFF;
        const float* src = (m == 0) ? w0 : (m == 1) ? w1 : (m == 2) ? w2 : k2;
        g_wt[m][o] = f2tf32f(src[o]);
    }
}

// ---------------------------------------------------------------------------
// 2) Router: argmax of logits (softmax monotone; top-1 weight == 1 exactly)
// ---------------------------------------------------------------------------
__global__ void route_kernel(const float* __restrict__ rw, const float* __restrict__ rb) {
    int b = threadIdx.x;
    if (b >= NB) return;
    float best = -1e30f; int bi = 0;
    #pragma unroll
    for (int j = 0; j < 3; j++) {
        float s = rb[j];
        const float* w = rw + j*NC;
        const float* p = g_pooled + b*NC;
        for (int c = 0; c < NC; c++) s = fmaf(p[c], w[c], s);
        if (s > best) { best = s; bi = j; }
    }
    g_idx[b] = bi;
}

// ---------------------------------------------------------------------------
// Depthwise 3x3 conv (dil D) + BN + exact GELU — smem-tiled plane.
// ---------------------------------------------------------------------------
#define SMC 70

template<int D>
__device__ __forceinline__ void dwconv_plane(
    float (*sm)[SMC], const float* __restrict__ xp, const float* __restrict__ kw9,
    float scale, float mm, float bb, float* __restrict__ outp)
{
    const int tid = threadIdx.x;

    for (int i = tid; i < 272; i += 256) {
        int r = i / 68, c = i % 68;
        sm[(r < 2) ? r : r + 64][c] = 0.f;
    }
    {
        int r = 2 + (tid >> 2);
        int c = tid & 3;
        sm[r][(c < 2) ? c : c + 64] = 0.f;
    }

    #pragma unroll
    for (int i = 0; i < 4; i++) {
        int idx = tid + i*256;
        int y = idx >> 4, x4 = (idx & 15) * 4;
        float4 v = reinterpret_cast<const float4*>(xp)[idx];
        sm[y+2][x4+2+0] = v.x;
        sm[y+2][x4+2+1] = v.y;
        sm[y+2][x4+2+2] = v.z;
        sm[y+2][x4+2+3] = v.w;
    }
    __syncthreads();

    const int y  = tid >> 2;
    const int x0 = (tid & 3) * 16;

    float acc[16];
    #pragma unroll
    for (int j = 0; j < 16; j++) acc[j] = 0.f;

    #pragma unroll
    for (int dy = 0; dy < 3; dy++) {
        const float* row = &sm[y + 2 + (dy-1)*D][x0 + 2 - D];
        const float w0 = kw9[dy*3 + 0];
        const float w1 = kw9[dy*3 + 1];
        const float w2 = kw9[dy*3 + 2];
        float v[16 + 2*D];
        #pragma unroll
        for (int j = 0; j < 16 + 2*D; j++) v[j] = row[j];
        #pragma unroll
        for (int j = 0; j < 16; j++)
            acc[j] = fmaf(w0, v[j], fmaf(w1, v[j+D], fmaf(w2, v[j+2*D], acc[j])));
    }

    float* op = outp + y*NW + x0;
    #pragma unroll
    for (int q = 0; q < 4; q++) {
        float4 o;
        float* oe = &o.x;
        #pragma unroll
        for (int j = 0; j < 4; j++) {
            float z = (acc[q*4 + j] - mm) * scale + bb;
            oe[j] = f2tf32f(gelu_exact(z));
        }
        reinterpret_cast<float4*>(op)[q] = o;
    }
}

// ---------------------------------------------------------------------------
// TF32 mma.sync GEMM tile, LDS.128 fragment layouts (proven R6 design),
// parameterized on smem base + tile coords.
// ---------------------------------------------------------------------------
__device__ __forceinline__ void mma_tf32(float c[4], const uint32_t a[4], const uint32_t b[2]) {
    asm volatile(
        "mma.sync.aligned.m16n8k8.row.col.f32.tf32.tf32.f32 "
        "{%0,%1,%2,%3}, {%4,%5,%6,%7}, {%8,%9}, {%0,%1,%2,%3};"
        : "+f"(c[0]), "+f"(c[1]), "+f"(c[2]), "+f"(c[3])
        : "r"(a[0]), "r"(a[1]), "r"(a[2]), "r"(a[3]),
          "r"(b[0]), "r"(b[1]));
}

#define SPB 136
#define GEMM_SMEM (2*128*16*4 + 2*16*SPB*4)   // 16384 + 17408 = 33792

template<bool BN_GELU, bool CVTB>
__device__ __forceinline__ void mma_gemm_tile(
    char* smembase,
    const float* __restrict__ A, const float* __restrict__ Bm, float* __restrict__ Cm,
    const float* __restrict__ p0, const float* __restrict__ p1,
    const float* __restrict__ p2, const float* __restrict__ p3,
    int m0, int n0)
{
    uint32_t (*As)[128*16]   = reinterpret_cast<uint32_t (*)[128*16]>(smembase);
    uint32_t (*Bs)[16][SPB]  = reinterpret_cast<uint32_t (*)[16][SPB]>(smembase + 2*128*16*4);

    const int tid  = threadIdx.x;
    const int lane = tid & 31;
    const int wid  = tid >> 5;
    const int wm   = wid & 3;
    const int wn   = wid >> 2;
    const int gID  = lane >> 2;
    const int qid  = lane & 3;

    const int am = tid >> 1;
    const int ah = tid & 1;
    const uint32_t hA = (uint32_t)((am ^ (am >> 2)) & 3);
    const float* aSrc = A + (size_t)(m0 + am) * NC + ah*8;

    const int bk0 = tid >> 5;
    const int bn  = (tid & 31) * 4;
    const float* bSrc = Bm + (size_t)bk0 * NHW + n0 + bn;

    int bcol[4];
    #pragma unroll
    for (int j = 0; j < 4; j++) {
        int n = bn + j;
        bcol[j] = ((n >> 5) << 5) + ((n & 7) << 2) + ((n >> 3) & 3);
    }

    float acc[2][8][4];
    #pragma unroll
    for (int i = 0; i < 2; i++)
        #pragma unroll
        for (int j = 0; j < 8; j++)
            #pragma unroll
            for (int t = 0; t < 4; t++) acc[i][j][t] = 0.f;

    {
        float4 fa0 = *reinterpret_cast<const float4*>(aSrc);
        float4 fa1 = *reinterpret_cast<const float4*>(aSrc + 4);
        float4 fb0 = *reinterpret_cast<const float4*>(bSrc);
        float4 fb1 = *reinterpret_cast<const float4*>(bSrc + (size_t)8 * NHW);
        #pragma unroll
        for (int j = 0; j < 4; j++) {
            uint32_t off = am*16 + ((j ^ hA) << 2) + ah*2;
            *reinterpret_cast<uint2*>(&As[0][off]) =
                make_uint2(__float_as_uint((&fa0.x)[j]), __float_as_uint((&fa1.x)[j]));
            uint32_t v0 = CVTB ? f2tf32((&fb0.x)[j]) : __float_as_uint((&fb0.x)[j]);
            uint32_t v1 = CVTB ? f2tf32((&fb1.x)[j]) : __float_as_uint((&fb1.x)[j]);
            Bs[0][bk0][bcol[j]]     = v0;
            Bs[0][bk0 + 8][bcol[j]] = v1;
        }
    }
    __syncthreads();

    int buf = 0;
    for (int kc = 0; kc < 16; kc++) {
        const bool has_next = (kc + 1) < 16;
        float4 fa0, fa1, fb0, fb1;
        if (has_next) {
            const int kn = (kc + 1) * 16;
            fa0 = *reinterpret_cast<const float4*>(aSrc + kn);
            fa1 = *reinterpret_cast<const float4*>(aSrc + kn + 4);
            fb0 = *reinterpret_cast<const float4*>(bSrc + (size_t)kn * NHW);
            fb1 = *reinterpret_cast<const float4*>(bSrc + (size_t)(kn + 8) * NHW);
        }

        uint4 aq[2][2];
        #pragma unroll
        for (int mt = 0; mt < 2; mt++)
            #pragma unroll
            for (int mh = 0; mh < 2; mh++) {
                int m = wm*32 + mt*16 + mh*8 + gID;
                uint32_t off = m*16 + (((qid ^ ((m ^ (m >> 2)) & 3))) << 2);
                aq[mt][mh] = *reinterpret_cast<const uint4*>(&As[buf][off]);
            }

        #pragma unroll
        for (int ks = 0; ks < 2; ks++) {
            uint4 bq[2][2];
            #pragma unroll
            for (int kh = 0; kh < 2; kh++)
                #pragma unroll
                for (int bl = 0; bl < 2; bl++) {
                    int krow = ks*8 + kh*4 + qid;
                    int ncol = (wn*2 + bl)*32 + gID*4;
                    bq[kh][bl] = *reinterpret_cast<const uint4*>(&Bs[buf][krow][ncol]);
                }

            #pragma unroll
            for (int mt = 0; mt < 2; mt++) {
                uint32_t a[4];
                if (ks == 0) {
                    a[0] = aq[mt][0].x; a[1] = aq[mt][1].x;
                    a[2] = aq[mt][0].y; a[3] = aq[mt][1].y;
                } else {
                    a[0] = aq[mt][0].z; a[1] = aq[mt][1].z;
                    a[2] = aq[mt][0].w; a[3] = aq[mt][1].w;
                }
                #pragma unroll
                for (int bl = 0; bl < 2; bl++) {
                    #pragma unroll
                    for (int c = 0; c < 4; c++) {
                        uint32_t b[2];
                        b[0] = (&bq[0][bl].x)[c];
                        b[1] = (&bq[1][bl].x)[c];
                        mma_tf32(acc[mt][bl*4 + c], a, b);
                    }
                }
            }
        }

        if (has_next) {
            const int nb_ = buf ^ 1;
            #pragma unroll
            for (int j = 0; j < 4; j++) {
                uint32_t off = am*16 + ((j ^ hA) << 2) + ah*2;
                *reinterpret_cast<uint2*>(&As[nb_][off]) =
                    make_uint2(__float_as_uint((&fa0.x)[j]), __float_as_uint((&fa1.x)[j]));
                uint32_t v0 = CVTB ? f2tf32((&fb0.x)[j]) : __float_as_uint((&fb0.x)[j]);
                uint32_t v1 = CVTB ? f2tf32((&fb1.x)[j]) : __float_as_uint((&fb1.x)[j]);
                Bs[nb_][bk0][bcol[j]]     = v0;
                Bs[nb_][bk0 + 8][bcol[j]] = v1;
            }
            __syncthreads();
            buf = nb_;
        }
    }

    #pragma unroll
    for (int mt = 0; mt < 2; mt++) {
        #pragma unroll
        for (int half = 0; half < 2; half++) {
            const int o = m0 + wm*32 + mt*16 + half*8 + gID;
            float sc = 0.f, mm = 0.f, bb;
            if (BN_GELU) {
                sc = p0[o] * rsqrtf(p3[o] + EPSV);
                mm = p2[o];
                bb = p1[o];
            } else {
                bb = p0[o];
            }
            float* cp = Cm + (size_t)o * NHW + n0 + wn*64 + qid*2;
            #pragma unroll
            for (int nt = 0; nt < 8; nt++) {
                float z0 = acc[mt][nt][half*2 + 0];
                float z1 = acc[mt][nt][half*2 + 1];
                if (BN_GELU) {
                    z0 = (z0 - mm) * sc + bb; z0 = f2tf32f(gelu_exact(z0));
                    z1 = (z1 - mm) * sc + bb; z1 = f2tf32f(gelu_exact(z1));
                } else {
                    z0 += bb; z1 += bb;
                }
                *reinterpret_cast<float2*>(cp + nt*8) = make_float2(z0, z1);
            }
        }
    }
}

// ---------------------------------------------------------------------------
// 3) Fused feature stage: interleaved dwconv planes (4/5 of blocks, experts
//    0/1) and expert-2 feature GEMM tiles (1/5 of blocks). Disjoint batches
//    -> concurrent execution instead of two serialized launches.
// ---------------------------------------------------------------------------
__global__ void __launch_bounds__(256, 2) feature_kernel(
    const float* __restrict__ x,
    const float* __restrict__ k0, const float* __restrict__ g0, const float* __restrict__ b0,
    const float* __restrict__ m0_, const float* __restrict__ v0,
    const float* __restrict__ k1, const float* __restrict__ g1, const float* __restrict__ b1,
    const float* __restrict__ m1, const float* __restrict__ v1,
    const float* __restrict__ g2, const float* __restrict__ b2,
    const float* __restrict__ m2, const float* __restrict__ v2)
{
    __shared__ __align__(16) char usm[GEMM_SMEM];   // 33792 >= dwconv's 19040
    const int id = blockIdx.x;

    if ((id % 5) == 4) {
        // ---- feat GEMM tile (2048 of 10240) ----
        const int t = id / 5;            // 0..2047
        const int b = t >> 6;            // 32 batches
        const int r = t & 63;            // 2 m-tiles x 32 n-tiles
        if (g_idx[b] != 2) return;
        mma_gemm_tile<true, true>(usm, g_wt[3], x + (size_t)b*NCHW, g_feat + (size_t)b*NCHW,
                                  g2, b2, m2, v2, (r >> 5) * 128, (r & 31) * 128);
    } else {
        // ---- dwconv plane (8192 of 10240) ----
        const int dw = (id / 5) * 4 + (id % 5);   // 0..8191
        const int b = dw >> 8;
        const int e = g_idx[b];
        if (e == 2) return;
        const int c = dw & 255;

        float (*sm)[SMC] = reinterpret_cast<float (*)[SMC]>(usm);
        const float gg = (e == 0 ? g0[c] : g1[c]);
        const float vv = (e == 0 ? v0[c] : v1[c]);
        const float mm = (e == 0 ? m0_[c] : m1[c]);
        const float bb = (e == 0 ? b0[c] : b1[c]);
        const float scale = gg * rsqrtf(vv + EPSV);
        const float* kw = (e == 0 ? k0 : k1) + c * 9;
        const float* xp = x + ((size_t)b*NC + c) * NHW;
        float* outp = g_feat + ((size_t)b*NC + c) * NHW;

        if (e == 0) dwconv_plane<1>(sm, xp, kw, scale, mm, bb, outp);
        else        dwconv_plane<2>(sm, xp, kw, scale, mm, bb, outp);
    }
}

// 4) Final pointwise: out[b] = e{idx}_pw @ feat[b] + e{idx}_pb
__global__ void __launch_bounds__(256, 2) out_gemm_kernel(
    const float* __restrict__ pb0, const float* __restrict__ pb1,
    const float* __restrict__ pb2, float* __restrict__ out)
{
    __shared__ __align__(16) char usm[GEMM_SMEM];
    int b = blockIdx.z;
    int e = g_idx[b];
    const float* pb = (e == 0) ? pb0 : (e == 1 ? pb1 : pb2);
    mma_gemm_tile<false, false>(usm, g_wt[e], g_feat + (size_t)b*NCHW, out + (size_t)b*NCHW,
                                pb, nullptr, nullptr, nullptr,
                                blockIdx.y * 128, blockIdx.x * 128);
}

// ---------------------------------------------------------------------------
extern "C" void kernel_launch(void* const* d_in, const int* in_sizes, int n_in,
                              void* d_out, int out_size) {
    const float* x    = (const float*)d_in[0];
    const float* rw   = (const float*)d_in[1];
    const float* rb   = (const float*)d_in[2];
    const float* e0_k = (const float*)d_in[3];
    const float* e0_g = (const float*)d_in[4];
    const float* e0_b = (const float*)d_in[5];
    const float* e0_m = (const float*)d_in[6];
    const float* e0_v = (const float*)d_in[7];
    const float* e0_pw= (const float*)d_in[8];
    const float* e0_pb= (const float*)d_in[9];
    const float* e1_k = (const float*)d_in[10];
    const float* e1_g = (const float*)d_in[11];
    const float* e1_b = (const float*)d_in[12];
    const float* e1_m = (const float*)d_in[13];
    const float* e1_v = (const float*)d_in[14];
    const float* e1_pw= (const float*)d_in[15];
    const float* e1_pb= (const float*)d_in[16];
    const float* e2_k = (const float*)d_in[17];
    const float* e2_g = (const float*)d_in[18];
    const float* e2_b = (const float*)d_in[19];
    const float* e2_m = (const float*)d_in[20];
    const float* e2_v = (const float*)d_in[21];
    const float* e2_pw= (const float*)d_in[22];
    const float* e2_pb= (const float*)d_in[23];
    float* out = (float*)d_out;

    pool_prep_kernel<<<NB*NC + 1024, 256>>>(x, e0_pw, e1_pw, e2_pw, e2_k);
    route_kernel<<<1, 32>>>(rw, rb);

    feature_kernel<<<10240, 256>>>(
        x, e0_k, e0_g, e0_b, e0_m, e0_v,
           e1_k, e1_g, e1_b, e1_m, e1_v,
           e2_g, e2_b, e2_m, e2_v);

    dim3 ggrid(NHW/128, NC/128, NB);   // (32, 2, 32)
    out_gemm_kernel<<<ggrid, 256>>>(e0_pb, e1_pb, e2_pb, out);
}

// round 11
// speedup vs baseline: 1.1990x; 1.1990x over previous
#include <cuda_runtime.h>
#include <math.h>
#include <stdint.h>

#define NB 32
#define NC 256
#define NH 64
#define NW 64
#define NHW 4096
#define NCHW (NC*NHW)
#define EPSV 1e-5f

// Scratch (allocation-free rule: __device__ globals)
__device__ float g_pooled[NB*NC];
__device__ int   g_idx[NB];
__device__ float g_feat[(size_t)NB*NCHW];   // tf32-rounded feature scratch
__device__ float g_wt[4][NC*NC];            // tf32-rounded weights: e0_pw,e1_pw,e2_pw,e2_k

__device__ __forceinline__ uint32_t f2tf32(float f) {
    uint32_t r;
    asm("cvt.rna.tf32.f32 %0, %1;" : "=r"(r) : "f"(f));
    return r;
}
__device__ __forceinline__ float f2tf32f(float f) { return __uint_as_float(f2tf32(f)); }

__device__ __forceinline__ float gelu_exact(float z) {
    return 0.5f * z * (1.0f + erff(z * 0.7071067811865475f));
}

__device__ __forceinline__ uint32_t smem_addr_u32(const void* p) {
    return (uint32_t)__cvta_generic_to_shared(p);
}
__device__ __forceinline__ void cp_async16(uint32_t dst, const void* src) {
    asm volatile("cp.async.ca.shared.global [%0], [%1], 16;" :: "r"(dst), "l"(src));
}
#define CP_COMMIT() asm volatile("cp.async.commit_group;")
#define CP_WAIT(n)  asm volatile("cp.async.wait_group %0;" :: "n"(n))

// ---------------------------------------------------------------------------
// 1) Fused: global average pool + weight pre-convert
// ---------------------------------------------------------------------------
__global__ void pool_prep_kernel(const float* __restrict__ x,
                                 const float* __restrict__ w0, const float* __restrict__ w1,
                                 const float* __restrict__ w2, const float* __restrict__ k2) {
    if (blockIdx.x < NB*NC) {
        int bc = blockIdx.x;
        const float4* p = reinterpret_cast<const float4*>(x + (size_t)bc * NHW);
        float s = 0.f;
        for (int i = threadIdx.x; i < NHW/4; i += 256) {
            float4 v = p[i];
            s += (v.x + v.y) + (v.z + v.w);
        }
        __shared__ float red[8];
        #pragma unroll
        for (int o = 16; o > 0; o >>= 1) s += __shfl_down_sync(0xffffffffu, s, o);
        if ((threadIdx.x & 31) == 0) red[threadIdx.x >> 5] = s;
        __syncthreads();
        if (threadIdx.x < 8) {
            float t = red[threadIdx.x];
            #pragma unroll
            for (int o = 4; o > 0; o >>= 1) t += __shfl_down_sync(0xffu, t, o);
            if (threadIdx.x == 0) g_pooled[bc] = t * (1.0f / NHW);
        }
    } else {
        int i = (blockIdx.x - NB*NC) * 256 + threadIdx.x;
        int m = i >> 16;
        int o = i & 0xFFFF;
        const float* src = (m == 0) ? w0 : (m == 1) ? w1 : (m == 2) ? w2 : k2;
        g_wt[m][o] = f2tf32f(src[o]);
    }
}

// ---------------------------------------------------------------------------
// 2) Router
// ---------------------------------------------------------------------------
__global__ void route_kernel(const float* __restrict__ rw, const float* __restrict__ rb) {
    int b = threadIdx.x;
    if (b >= NB) return;
    float best = -1e30f; int bi = 0;
    #pragma unroll
    for (int j = 0; j < 3; j++) {
        float s = rb[j];
        const float* w = rw + j*NC;
        const float* p = g_pooled + b*NC;
        for (int c = 0; c < NC; c++) s = fmaf(p[c], w[c], s);
        if (s > best) { best = s; bi = j; }
    }
    g_idx[b] = bi;
}

// ---------------------------------------------------------------------------
// 3a) Depthwise 3x3 conv + BN + exact GELU (R9-proven)
// ---------------------------------------------------------------------------
#define SMC 70

template<int D>
__device__ __forceinline__ void dwconv_plane(
    float (*sm)[SMC], const float* __restrict__ xp, const float* __restrict__ kw9,
    float scale, float mm, float bb, float* __restrict__ outp)
{
    const int tid = threadIdx.x;

    for (int i = tid; i < 272; i += 256) {
        int r = i / 68, c = i % 68;
        sm[(r < 2) ? r : r + 64][c] = 0.f;
    }
    {
        int r = 2 + (tid >> 2);
        int c = tid & 3;
        sm[r][(c < 2) ? c : c + 64] = 0.f;
    }

    #pragma unroll
    for (int i = 0; i < 4; i++) {
        int idx = tid + i*256;
        int y = idx >> 4, x4 = (idx & 15) * 4;
        float4 v = reinterpret_cast<const float4*>(xp)[idx];
        sm[y+2][x4+2+0] = v.x;
        sm[y+2][x4+2+1] = v.y;
        sm[y+2][x4+2+2] = v.z;
        sm[y+2][x4+2+3] = v.w;
    }
    __syncthreads();

    const int y  = tid >> 2;
    const int x0 = (tid & 3) * 16;

    float acc[16];
    #pragma unroll
    for (int j = 0; j < 16; j++) acc[j] = 0.f;

    #pragma unroll
    for (int dy = 0; dy < 3; dy++) {
        const float* row = &sm[y + 2 + (dy-1)*D][x0 + 2 - D];
        const float w0 = kw9[dy*3 + 0];
        const float w1 = kw9[dy*3 + 1];
        const float w2 = kw9[dy*3 + 2];
        float v[16 + 2*D];
        #pragma unroll
        for (int j = 0; j < 16 + 2*D; j++) v[j] = row[j];
        #pragma unroll
        for (int j = 0; j < 16; j++)
            acc[j] = fmaf(w0, v[j], fmaf(w1, v[j+D], fmaf(w2, v[j+2*D], acc[j])));
    }

    float* op = outp + y*NW + x0;
    #pragma unroll
    for (int q = 0; q < 4; q++) {
        float4 o;
        float* oe = &o.x;
        #pragma unroll
        for (int j = 0; j < 4; j++) {
            float z = (acc[q*4 + j] - mm) * scale + bb;
            oe[j] = f2tf32f(gelu_exact(z));
        }
        reinterpret_cast<float4*>(op)[q] = o;
    }
}

__global__ void __launch_bounds__(256) dwconv_bn_gelu_kernel(
    const float* __restrict__ x,
    const float* __restrict__ k0, const float* __restrict__ g0, const float* __restrict__ b0,
    const float* __restrict__ m0, const float* __restrict__ v0,
    const float* __restrict__ k1, const float* __restrict__ g1, const float* __restrict__ b1,
    const float* __restrict__ m1, const float* __restrict__ v1)
{
    __shared__ float sm[68][SMC];
    const int b = blockIdx.y;
    const int e = g_idx[b];
    if (e == 2) return;
    const int c = blockIdx.x;

    const float gg = (e == 0 ? g0[c] : g1[c]);
    const float vv = (e == 0 ? v0[c] : v1[c]);
    const float mm = (e == 0 ? m0[c] : m1[c]);
    const float bb = (e == 0 ? b0[c] : b1[c]);
    const float scale = gg * rsqrtf(vv + EPSV);
    const float* kw = (e == 0 ? k0 : k1) + c * 9;
    const float* xp = x + ((size_t)b*NC + c) * NHW;
    float* outp = g_feat + ((size_t)b*NC + c) * NHW;

    if (e == 0) dwconv_plane<1>(sm, xp, kw, scale, mm, bb, outp);
    else        dwconv_plane<2>(sm, xp, kw, scale, mm, bb, outp);
}

// ---------------------------------------------------------------------------
// mma.sync tf32 primitive
// ---------------------------------------------------------------------------
__device__ __forceinline__ void mma_tf32(float c[4], const uint32_t a[4], const uint32_t b[2]) {
    asm volatile(
        "mma.sync.aligned.m16n8k8.row.col.f32.tf32.tf32.f32 "
        "{%0,%1,%2,%3}, {%4,%5,%6,%7}, {%8,%9}, {%0,%1,%2,%3};"
        : "+f"(c[0]), "+f"(c[1]), "+f"(c[2]), "+f"(c[3])
        : "r"(a[0]), "r"(a[1]), "r"(a[2]), "r"(a[3]),
          "r"(b[0]), "r"(b[1]));
}

// ---------------------------------------------------------------------------
// feat GEMM: R6/R9-proven tile (register staging, LDS.128 everywhere)
// ---------------------------------------------------------------------------
#define SPB 136

__global__ void __launch_bounds__(256, 2) feat_gemm_kernel(
    const float* __restrict__ x,
    const float* __restrict__ p0, const float* __restrict__ p1,
    const float* __restrict__ p2, const float* __restrict__ p3)
{
    int bz = blockIdx.z;
    if (g_idx[bz] != 2) return;
    const float* A  = g_wt[3];
    const float* Bm = x + (size_t)bz*NCHW;
    float* Cm = g_feat + (size_t)bz*NCHW;

    __shared__ __align__(16) uint32_t As[2][128*16];
    __shared__ __align__(16) uint32_t Bs[2][16][SPB];

    const int tid  = threadIdx.x;
    const int lane = tid & 31;
    const int wid  = tid >> 5;
    const int wm   = wid & 3;
    const int wn   = wid >> 2;
    const int gID  = lane >> 2;
    const int qid  = lane & 3;
    const int m0   = blockIdx.y * 128;
    const int n0   = blockIdx.x * 128;

    const int am = tid >> 1;
    const int ah = tid & 1;
    const uint32_t hA = (uint32_t)((am ^ (am >> 2)) & 3);
    const float* aSrc = A + (size_t)(m0 + am) * NC + ah*8;

    const int bk0 = tid >> 5;
    const int bn  = (tid & 31) * 4;
    const float* bSrc = Bm + (size_t)bk0 * NHW + n0 + bn;

    int bcol[4];
    #pragma unroll
    for (int j = 0; j < 4; j++) {
        int n = bn + j;
        bcol[j] = ((n >> 5) << 5) + ((n & 7) << 2) + ((n >> 3) & 3);
    }

    float acc[2][8][4];
    #pragma unroll
    for (int i = 0; i < 2; i++)
        #pragma unroll
        for (int j = 0; j < 8; j++)
            #pragma unroll
            for (int t = 0; t < 4; t++) acc[i][j][t] = 0.f;

    {
        float4 fa0 = *reinterpret_cast<const float4*>(aSrc);
        float4 fa1 = *reinterpret_cast<const float4*>(aSrc + 4);
        float4 fb0 = *reinterpret_cast<const float4*>(bSrc);
        float4 fb1 = *reinterpret_cast<const float4*>(bSrc + (size_t)8 * NHW);
        #pragma unroll
        for (int j = 0; j < 4; j++) {
            uint32_t off = am*16 + ((j ^ hA) << 2) + ah*2;
            *reinterpret_cast<uint2*>(&As[0][off]) =
                make_uint2(__float_as_uint((&fa0.x)[j]), __float_as_uint((&fa1.x)[j]));
            Bs[0][bk0][bcol[j]]     = f2tf32((&fb0.x)[j]);
            Bs[0][bk0 + 8][bcol[j]] = f2tf32((&fb1.x)[j]);
        }
    }
    __syncthreads();

    int buf = 0;
    for (int kc = 0; kc < 16; kc++) {
        const bool has_next = (kc + 1) < 16;
        float4 fa0, fa1, fb0, fb1;
        if (has_next) {
            const int kn = (kc + 1) * 16;
            fa0 = *reinterpret_cast<const float4*>(aSrc + kn);
            fa1 = *reinterpret_cast<const float4*>(aSrc + kn + 4);
            fb0 = *reinterpret_cast<const float4*>(bSrc + (size_t)kn * NHW);
            fb1 = *reinterpret_cast<const float4*>(bSrc + (size_t)(kn + 8) * NHW);
        }

        uint4 aq[2][2];
        #pragma unroll
        for (int mt = 0; mt < 2; mt++)
            #pragma unroll
            for (int mh = 0; mh < 2; mh++) {
                int m = wm*32 + mt*16 + mh*8 + gID;
                uint32_t off = m*16 + (((qid ^ ((m ^ (m >> 2)) & 3))) << 2);
                aq[mt][mh] = *reinterpret_cast<const uint4*>(&As[buf][off]);
            }

        #pragma unroll
        for (int ks = 0; ks < 2; ks++) {
            uint4 bq[2][2];
            #pragma unroll
            for (int kh = 0; kh < 2; kh++)
                #pragma unroll
                for (int bl = 0; bl < 2; bl++) {
                    int krow = ks*8 + kh*4 + qid;
                    int ncol = (wn*2 + bl)*32 + gID*4;
                    bq[kh][bl] = *reinterpret_cast<const uint4*>(&Bs[buf][krow][ncol]);
                }

            #pragma unroll
            for (int mt = 0; mt < 2; mt++) {
                uint32_t a[4];
                if (ks == 0) {
                    a[0] = aq[mt][0].x; a[1] = aq[mt][1].x;
                    a[2] = aq[mt][0].y; a[3] = aq[mt][1].y;
                } else {
                    a[0] = aq[mt][0].z; a[1] = aq[mt][1].z;
                    a[2] = aq[mt][0].w; a[3] = aq[mt][1].w;
                }
                #pragma unroll
                for (int bl = 0; bl < 2; bl++) {
                    #pragma unroll
                    for (int c = 0; c < 4; c++) {
                        uint32_t b[2];
                        b[0] = (&bq[0][bl].x)[c];
                        b[1] = (&bq[1][bl].x)[c];
                        mma_tf32(acc[mt][bl*4 + c], a, b);
                    }
                }
            }
        }

        if (has_next) {
            const int nb_ = buf ^ 1;
            #pragma unroll
            for (int j = 0; j < 4; j++) {
                uint32_t off = am*16 + ((j ^ hA) << 2) + ah*2;
                *reinterpret_cast<uint2*>(&As[nb_][off]) =
                    make_uint2(__float_as_uint((&fa0.x)[j]), __float_as_uint((&fa1.x)[j]));
                Bs[nb_][bk0][bcol[j]]     = f2tf32((&fb0.x)[j]);
                Bs[nb_][bk0 + 8][bcol[j]] = f2tf32((&fb1.x)[j]);
            }
            __syncthreads();
            buf = nb_;
        }
    }

    #pragma unroll
    for (int mt = 0; mt < 2; mt++) {
        #pragma unroll
        for (int half = 0; half < 2; half++) {
            const int o = m0 + wm*32 + mt*16 + half*8 + gID;
            float sc = p0[o] * rsqrtf(p3[o] + EPSV);
            float mm = p2[o];
            float bb = p1[o];
            float* cp = Cm + (size_t)o * NHW + n0 + wn*64 + qid*2;
            #pragma unroll
            for (int nt = 0; nt < 8; nt++) {
                float z0 = acc[mt][nt][half*2 + 0];
                float z1 = acc[mt][nt][half*2 + 1];
                z0 = (z0 - mm) * sc + bb; z0 = f2tf32f(gelu_exact(z0));
                z1 = (z1 - mm) * sc + bb; z1 = f2tf32f(gelu_exact(z1));
                *reinterpret_cast<float2*>(cp + nt*8) = make_float2(z0, z1);
            }
        }
    }
}

// ---------------------------------------------------------------------------
// out GEMM v3: cp.async 3-stage B pipeline (prefetch distance 2).
// A: LDS.128 interleaved layout, register-staged from L2 (g_wt).
// B: plain [k][136] rows, cp.async 16B chunks, scalar frag LDS (qid*8+gID
//    bank pattern = 0..31 distinct -> conflict-free).
// ---------------------------------------------------------------------------
__global__ void __launch_bounds__(256, 2) out_gemm_kernel(
    const float* __restrict__ pb0, const float* __restrict__ pb1,
    const float* __restrict__ pb2, float* __restrict__ out)
{
    __shared__ __align__(16) uint32_t As[2][128*16];
    __shared__ __align__(16) uint32_t Bs[3][16][SPB];

    const int bz = blockIdx.z;
    const int e  = g_idx[bz];
    const float* A  = g_wt[e];
    const float* pb = (e == 0) ? pb0 : (e == 1 ? pb1 : pb2);
    const float* Bm = g_feat + (size_t)bz*NCHW;
    float* Cm = out + (size_t)bz*NCHW;

    const int tid  = threadIdx.x;
    const int lane = tid & 31;
    const int wid  = tid >> 5;
    const int wm   = wid & 3;
    const int wn   = wid >> 2;
    const int gID  = lane >> 2;
    const int qid  = lane & 3;
    const int m0   = blockIdx.y * 128;
    const int n0   = blockIdx.x * 128;

    // A staging map
    const int am = tid >> 1;
    const int ah = tid & 1;
    const uint32_t hA = (uint32_t)((am ^ (am >> 2)) & 3);
    const float* aSrc = A + (size_t)(m0 + am) * NC + ah*8;

    // B cp.async map: 2 chunks of 16B per thread per stage
    const int bkA = tid >> 5;            // k row 0..7
    const int bj  = tid & 31;            // 16B chunk within row
    const uint32_t bs0 = smem_addr_u32(&Bs[0][0][0]);
    const uint32_t bDst0 = bs0 + (uint32_t)bkA       * (SPB*4) + (uint32_t)bj * 16;
    const uint32_t bDst1 = bs0 + (uint32_t)(bkA + 8) * (SPB*4) + (uint32_t)bj * 16;
    const float* bSrc = Bm + (size_t)bkA * NHW + n0 + bj*4;
    const uint32_t stageBytes = 16 * SPB * 4;

    float acc[2][8][4];
    #pragma unroll
    for (int i = 0; i < 2; i++)
        #pragma unroll
        for (int j = 0; j < 8; j++)
            #pragma unroll
            for (int t = 0; t < 4; t++) acc[i][j][t] = 0.f;

    // ---- prologue: B(0)->stage0, B(1)->stage1; A(0) regs -> As[0] ----
    cp_async16(bDst0, bSrc);
    cp_async16(bDst1, bSrc + (size_t)8 * NHW);
    CP_COMMIT();
    cp_async16(bDst0 + stageBytes, bSrc + (size_t)16 * NHW);
    cp_async16(bDst1 + stageBytes, bSrc + (size_t)24 * NHW);
    CP_COMMIT();
    {
        float4 fa0 = *reinterpret_cast<const float4*>(aSrc);
        float4 fa1 = *reinterpret_cast<const float4*>(aSrc + 4);
        #pragma unroll
        for (int j = 0; j < 4; j++) {
            uint32_t off = am*16 + ((j ^ hA) << 2) + ah*2;
            *reinterpret_cast<uint2*>(&As[0][off]) =
                make_uint2(__float_as_uint((&fa0.x)[j]), __float_as_uint((&fa1.x)[j]));
        }
    }
    CP_WAIT(1);          // B(0) complete
    __syncthreads();

    int bufA = 0;
    for (int kc = 0; kc < 16; kc++) {
        const int stage = kc % 3;

        // issue B(kc+2) into stage (kc+2)%3 (buffer freed: compute(kc-1) done at last sync)
        if (kc + 2 < 16) {
            const uint32_t so = (uint32_t)((kc + 2) % 3) * stageBytes;
            const float* s = bSrc + (size_t)(kc + 2) * 16 * NHW;
            cp_async16(bDst0 + so, s);
            cp_async16(bDst1 + so, s + (size_t)8 * NHW);
            CP_COMMIT();
        }
        // prefetch A(kc+1) (L2-resident weights)
        float4 fa0, fa1;
        const bool has_next = (kc + 1) < 16;
        if (has_next) {
            const int kn = (kc + 1) * 16;
            fa0 = *reinterpret_cast<const float4*>(aSrc + kn);
            fa1 = *reinterpret_cast<const float4*>(aSrc + kn + 4);
        }

        // ---- compute chunk kc: A from As[bufA], B from Bs[stage] ----
        uint4 aq[2][2];
        #pragma unroll
        for (int mt = 0; mt < 2; mt++)
            #pragma unroll
            for (int mh = 0; mh < 2; mh++) {
                int m = wm*32 + mt*16 + mh*8 + gID;
                uint32_t off = m*16 + (((qid ^ ((m ^ (m >> 2)) & 3))) << 2);
                aq[mt][mh] = *reinterpret_cast<const uint4*>(&As[bufA][off]);
            }

        #pragma unroll
        for (int ks = 0; ks < 2; ks++) {
            uint32_t bf[8][2];
            #pragma unroll
            for (int nt = 0; nt < 8; nt++) {
                int n = wn*64 + nt*8 + gID;
                bf[nt][0] = Bs[stage][ks*8 + qid]    [n];
                bf[nt][1] = Bs[stage][ks*8 + qid + 4][n];
            }
            #pragma unroll
            for (int mt = 0; mt < 2; mt++) {
                uint32_t a[4];
                if (ks == 0) {
                    a[0] = aq[mt][0].x; a[1] = aq[mt][1].x;
                    a[2] = aq[mt][0].y; a[3] = aq[mt][1].y;
                } else {
                    a[0] = aq[mt][0].z; a[1] = aq[mt][1].z;
                    a[2] = aq[mt][0].w; a[3] = aq[mt][1].w;
                }
                #pragma unroll
                for (int nt = 0; nt < 8; nt++)
                    mma_tf32(acc[mt][nt], a, bf[nt]);
            }
        }

        // stage A(kc+1) (overwrites buffer used by kc-1; safe: sync'd last iter)
        if (has_next) {
            const int nb_ = bufA ^ 1;
            #pragma unroll
            for (int j = 0; j < 4; j++) {
                uint32_t off = am*16 + ((j ^ hA) << 2) + ah*2;
                *reinterpret_cast<uint2*>(&As[nb_][off]) =
                    make_uint2(__float_as_uint((&fa0.x)[j]), __float_as_uint((&fa1.x)[j]));
            }
            bufA = nb_;
        }

        // ensure B(kc+1) complete for next iteration
        if (kc + 2 < 16) { CP_WAIT(1); } else { CP_WAIT(0); }
        __syncthreads();
    }

    // ---- epilogue ----
    #pragma unroll
    for (int mt = 0; mt < 2; mt++) {
        #pragma unroll
        for (int half = 0; half < 2; half++) {
            const int o = m0 + wm*32 + mt*16 + half*8 + gID;
            const float bb = pb[o];
            float* cp = Cm + (size_t)o * NHW + n0 + wn*64 + qid*2;
            #pragma unroll
            for (int nt = 0; nt < 8; nt++) {
                *reinterpret_cast<float2*>(cp + nt*8) =
                    make_float2(acc[mt][nt][half*2 + 0] + bb,
                                acc[mt][nt][half*2 + 1] + bb);
            }
        }
    }
}

// ---------------------------------------------------------------------------
extern "C" void kernel_launch(void* const* d_in, const int* in_sizes, int n_in,
                              void* d_out, int out_size) {
    const float* x    = (const float*)d_in[0];
    const float* rw   = (const float*)d_in[1];
    const float* rb   = (const float*)d_in[2];
    const float* e0_k = (const float*)d_in[3];
    const float* e0_g = (const float*)d_in[4];
    const float* e0_b = (const float*)d_in[5];
    const float* e0_m = (const float*)d_in[6];
    const float* e0_v = (const float*)d_in[7];
    const float* e0_pw= (const float*)d_in[8];
    const float* e0_pb= (const float*)d_in[9];
    const float* e1_k = (const float*)d_in[10];
    const float* e1_g = (const float*)d_in[11];
    const float* e1_b = (const float*)d_in[12];
    const float* e1_m = (const float*)d_in[13];
    const float* e1_v = (const float*)d_in[14];
    const float* e1_pw= (const float*)d_in[15];
    const float* e1_pb= (const float*)d_in[16];
    const float* e2_k = (const float*)d_in[17];
    const float* e2_g = (const float*)d_in[18];
    const float* e2_b = (const float*)d_in[19];
    const float* e2_m = (const float*)d_in[20];
    const float* e2_v = (const float*)d_in[21];
    const float* e2_pw= (const float*)d_in[22];
    const float* e2_pb= (const float*)d_in[23];
    float* out = (float*)d_out;

    pool_prep_kernel<<<NB*NC + 1024, 256>>>(x, e0_pw, e1_pw, e2_pw, e2_k);
    route_kernel<<<1, 32>>>(rw, rb);

    dwconv_bn_gelu_kernel<<<dim3(NC, NB), 256>>>(
        x, e0_k, e0_g, e0_b, e0_m, e0_v,
           e1_k, e1_g, e1_b, e1_m, e1_v);

    dim3 ggrid(NHW/128, NC/128, NB);   // (32, 2, 32)
    feat_gemm_kernel<<<ggrid, 256>>>(x, e2_g, e2_b, e2_m, e2_v);
    out_gemm_kernel<<<ggrid, 256>>>(e0_pb, e1_pb, e2_pb, out);
}

// round 12
// speedup vs baseline: 1.2452x; 1.0386x over previous
#include <cuda_runtime.h>
#include <math.h>
#include <stdint.h>

#define NB 32
#define NC 256
#define NH 64
#define NW 64
#define NHW 4096
#define NCHW (NC*NHW)
#define EPSV 1e-5f

// Scratch (allocation-free rule: __device__ globals)
__device__ float g_pooled[NB*NC];
__device__ int   g_idx[NB];
__device__ float g_feat[(size_t)NB*NCHW];   // tf32-rounded feature scratch
__device__ float g_wt[4][NC*NC];            // tf32-rounded weights: e0_pw,e1_pw,e2_pw,e2_k

__device__ __forceinline__ uint32_t f2tf32(float f) {
    uint32_t r;
    asm("cvt.rna.tf32.f32 %0, %1;" : "=r"(r) : "f"(f));
    return r;
}
__device__ __forceinline__ uint32_t u2tf32(uint32_t u) {
    uint32_t r;
    asm("cvt.rna.tf32.f32 %0, %1;" : "=r"(r) : "f"(__uint_as_float(u)));
    return r;
}
__device__ __forceinline__ float f2tf32f(float f) { return __uint_as_float(f2tf32(f)); }

__device__ __forceinline__ float gelu_exact(float z) {
    return 0.5f * z * (1.0f + erff(z * 0.7071067811865475f));
}

__device__ __forceinline__ uint32_t smem_addr_u32(const void* p) {
    return (uint32_t)__cvta_generic_to_shared(p);
}
__device__ __forceinline__ void cp_async16(uint32_t dst, const void* src) {
    asm volatile("cp.async.ca.shared.global [%0], [%1], 16;" :: "r"(dst), "l"(src));
}
#define CP_COMMIT() asm volatile("cp.async.commit_group;")
#define CP_WAIT(n)  asm volatile("cp.async.wait_group %0;" :: "n"(n))

// ---------------------------------------------------------------------------
// 1) Fused: global average pool + weight pre-convert
// ---------------------------------------------------------------------------
__global__ void pool_prep_kernel(const float* __restrict__ x,
                                 const float* __restrict__ w0, const float* __restrict__ w1,
                                 const float* __restrict__ w2, const float* __restrict__ k2) {
    if (blockIdx.x < NB*NC) {
        int bc = blockIdx.x;
        const float4* p = reinterpret_cast<const float4*>(x + (size_t)bc * NHW);
        float s = 0.f;
        for (int i = threadIdx.x; i < NHW/4; i += 256) {
            float4 v = p[i];
            s += (v.x + v.y) + (v.z + v.w);
        }
        __shared__ float red[8];
        #pragma unroll
        for (int o = 16; o > 0; o >>= 1) s += __shfl_down_sync(0xffffffffu, s, o);
        if ((threadIdx.x & 31) == 0) red[threadIdx.x >> 5] = s;
        __syncthreads();
        if (threadIdx.x < 8) {
            float t = red[threadIdx.x];
            #pragma unroll
            for (int o = 4; o > 0; o >>= 1) t += __shfl_down_sync(0xffu, t, o);
            if (threadIdx.x == 0) g_pooled[bc] = t * (1.0f / NHW);
        }
    } else {
        int i = (blockIdx.x - NB*NC) * 256 + threadIdx.x;
        int m = i >> 16;
        int o = i & 0xFFFF;
        const float* src = (m == 0) ? w0 : (m == 1) ? w1 : (m == 2) ? w2 : k2;
        g_wt[m][o] = f2tf32f(src[o]);
    }
}

// ---------------------------------------------------------------------------
// 2) Router
// ---------------------------------------------------------------------------
__global__ void route_kernel(const float* __restrict__ rw, const float* __restrict__ rb) {
    int b = threadIdx.x;
    if (b >= NB) return;
    float best = -1e30f; int bi = 0;
    #pragma unroll
    for (int j = 0; j < 3; j++) {
        float s = rb[j];
        const float* w = rw + j*NC;
        const float* p = g_pooled + b*NC;
        for (int c = 0; c < NC; c++) s = fmaf(p[c], w[c], s);
        if (s > best) { best = s; bi = j; }
    }
    g_idx[b] = bi;
}

// ---------------------------------------------------------------------------
// 3a) Depthwise 3x3 conv + BN + exact GELU (R9-proven)
// ---------------------------------------------------------------------------
#define SMC 70

template<int D>
__device__ __forceinline__ void dwconv_plane(
    float (*sm)[SMC], const float* __restrict__ xp, const float* __restrict__ kw9,
    float scale, float mm, float bb, float* __restrict__ outp)
{
    const int tid = threadIdx.x;

    for (int i = tid; i < 272; i += 256) {
        int r = i / 68, c = i % 68;
        sm[(r < 2) ? r : r + 64][c] = 0.f;
    }
    {
        int r = 2 + (tid >> 2);
        int c = tid & 3;
        sm[r][(c < 2) ? c : c + 64] = 0.f;
    }

    #pragma unroll
    for (int i = 0; i < 4; i++) {
        int idx = tid + i*256;
        int y = idx >> 4, x4 = (idx & 15) * 4;
        float4 v = reinterpret_cast<const float4*>(xp)[idx];
        sm[y+2][x4+2+0] = v.x;
        sm[y+2][x4+2+1] = v.y;
        sm[y+2][x4+2+2] = v.z;
        sm[y+2][x4+2+3] = v.w;
    }
    __syncthreads();

    const int y  = tid >> 2;
    const int x0 = (tid & 3) * 16;

    float acc[16];
    #pragma unroll
    for (int j = 0; j < 16; j++) acc[j] = 0.f;

    #pragma unroll
    for (int dy = 0; dy < 3; dy++) {
        const float* row = &sm[y + 2 + (dy-1)*D][x0 + 2 - D];
        const float w0 = kw9[dy*3 + 0];
        const float w1 = kw9[dy*3 + 1];
        const float w2 = kw9[dy*3 + 2];
        float v[16 + 2*D];
        #pragma unroll
        for (int j = 0; j < 16 + 2*D; j++) v[j] = row[j];
        #pragma unroll
        for (int j = 0; j < 16; j++)
            acc[j] = fmaf(w0, v[j], fmaf(w1, v[j+D], fmaf(w2, v[j+2*D], acc[j])));
    }

    float* op = outp + y*NW + x0;
    #pragma unroll
    for (int q = 0; q < 4; q++) {
        float4 o;
        float* oe = &o.x;
        #pragma unroll
        for (int j = 0; j < 4; j++) {
            float z = (acc[q*4 + j] - mm) * scale + bb;
            oe[j] = f2tf32f(gelu_exact(z));
        }
        reinterpret_cast<float4*>(op)[q] = o;
    }
}

__global__ void __launch_bounds__(256) dwconv_bn_gelu_kernel(
    const float* __restrict__ x,
    const float* __restrict__ k0, const float* __restrict__ g0, const float* __restrict__ b0,
    const float* __restrict__ m0, const float* __restrict__ v0,
    const float* __restrict__ k1, const float* __restrict__ g1, const float* __restrict__ b1,
    const float* __restrict__ m1, const float* __restrict__ v1)
{
    __shared__ float sm[68][SMC];
    const int b = blockIdx.y;
    const int e = g_idx[b];
    if (e == 2) return;
    const int c = blockIdx.x;

    const float gg = (e == 0 ? g0[c] : g1[c]);
    const float vv = (e == 0 ? v0[c] : v1[c]);
    const float mm = (e == 0 ? m0[c] : m1[c]);
    const float bb = (e == 0 ? b0[c] : b1[c]);
    const float scale = gg * rsqrtf(vv + EPSV);
    const float* kw = (e == 0 ? k0 : k1) + c * 9;
    const float* xp = x + ((size_t)b*NC + c) * NHW;
    float* outp = g_feat + ((size_t)b*NC + c) * NHW;

    if (e == 0) dwconv_plane<1>(sm, xp, kw, scale, mm, bb, outp);
    else        dwconv_plane<2>(sm, xp, kw, scale, mm, bb, outp);
}

// ---------------------------------------------------------------------------
// mma.sync tf32 primitive
// ---------------------------------------------------------------------------
__device__ __forceinline__ void mma_tf32(float c[4], const uint32_t a[4], const uint32_t b[2]) {
    asm volatile(
        "mma.sync.aligned.m16n8k8.row.col.f32.tf32.tf32.f32 "
        "{%0,%1,%2,%3}, {%4,%5,%6,%7}, {%8,%9}, {%0,%1,%2,%3};"
        : "+f"(c[0]), "+f"(c[1]), "+f"(c[2]), "+f"(c[3])
        : "r"(a[0]), "r"(a[1]), "r"(a[2]), "r"(a[3]),
          "r"(b[0]), "r"(b[1]));
}

#define SPB 136

// ---------------------------------------------------------------------------
// Pipelined GEMM core (proven on out_gemm): cp.async 3-stage B (distance 2),
// A via LDS.128 interleaved layout with register staging from L2.
// CVTB: B arrives raw fp32 in smem; convert RNA->tf32 on fragment registers
// (numerically identical to converting at staging).
// ---------------------------------------------------------------------------
template<bool CVTB>
__device__ __forceinline__ void pipe_gemm(
    uint32_t (*As)[128*16], uint32_t (*BsFlat),   // Bs: [3][16][SPB] flattened
    const float* __restrict__ A, const float* __restrict__ Bm,
    int m0, int n0, float acc[2][8][4])
{
    const int tid  = threadIdx.x;
    const int lane = tid & 31;
    const int wid  = tid >> 5;
    const int wm   = wid & 3;
    const int wn   = wid >> 2;
    const int gID  = lane >> 2;
    const int qid  = lane & 3;

    const int am = tid >> 1;
    const int ah = tid & 1;
    const uint32_t hA = (uint32_t)((am ^ (am >> 2)) & 3);
    const float* aSrc = A + (size_t)(m0 + am) * NC + ah*8;

    const int bkA = tid >> 5;
    const int bj  = tid & 31;
    const uint32_t bs0 = smem_addr_u32(BsFlat);
    const uint32_t bDst0 = bs0 + (uint32_t)bkA       * (SPB*4) + (uint32_t)bj * 16;
    const uint32_t bDst1 = bs0 + (uint32_t)(bkA + 8) * (SPB*4) + (uint32_t)bj * 16;
    const float* bSrc = Bm + (size_t)bkA * NHW + n0 + bj*4;
    const uint32_t stageBytes = 16 * SPB * 4;

    // prologue
    cp_async16(bDst0, bSrc);
    cp_async16(bDst1, bSrc + (size_t)8 * NHW);
    CP_COMMIT();
    cp_async16(bDst0 + stageBytes, bSrc + (size_t)16 * NHW);
    cp_async16(bDst1 + stageBytes, bSrc + (size_t)24 * NHW);
    CP_COMMIT();
    {
        float4 fa0 = *reinterpret_cast<const float4*>(aSrc);
        float4 fa1 = *reinterpret_cast<const float4*>(aSrc + 4);
        #pragma unroll
        for (int j = 0; j < 4; j++) {
            uint32_t off = am*16 + ((j ^ hA) << 2) + ah*2;
            *reinterpret_cast<uint2*>(&As[0][off]) =
                make_uint2(__float_as_uint((&fa0.x)[j]), __float_as_uint((&fa1.x)[j]));
        }
    }
    CP_WAIT(1);
    __syncthreads();

    int bufA = 0;
    for (int kc = 0; kc < 16; kc++) {
        const uint32_t* BsStage = BsFlat + (size_t)(kc % 3) * 16 * SPB;

        if (kc + 2 < 16) {
            const uint32_t so = (uint32_t)((kc + 2) % 3) * stageBytes;
            const float* s = bSrc + (size_t)(kc + 2) * 16 * NHW;
            cp_async16(bDst0 + so, s);
            cp_async16(bDst1 + so, s + (size_t)8 * NHW);
            CP_COMMIT();
        }
        float4 fa0, fa1;
        const bool has_next = (kc + 1) < 16;
        if (has_next) {
            const int kn = (kc + 1) * 16;
            fa0 = *reinterpret_cast<const float4*>(aSrc + kn);
            fa1 = *reinterpret_cast<const float4*>(aSrc + kn + 4);
        }

        uint4 aq[2][2];
        #pragma unroll
        for (int mt = 0; mt < 2; mt++)
            #pragma unroll
            for (int mh = 0; mh < 2; mh++) {
                int m = wm*32 + mt*16 + mh*8 + gID;
                uint32_t off = m*16 + (((qid ^ ((m ^ (m >> 2)) & 3))) << 2);
                aq[mt][mh] = *reinterpret_cast<const uint4*>(&As[bufA][off]);
            }

        #pragma unroll
        for (int ks = 0; ks < 2; ks++) {
            uint32_t bf[8][2];
            #pragma unroll
            for (int nt = 0; nt < 8; nt++) {
                int n = wn*64 + nt*8 + gID;
                uint32_t v0 = BsStage[(ks*8 + qid)     * SPB + n];
                uint32_t v1 = BsStage[(ks*8 + qid + 4) * SPB + n];
                bf[nt][0] = CVTB ? u2tf32(v0) : v0;
                bf[nt][1] = CVTB ? u2tf32(v1) : v1;
            }
            #pragma unroll
            for (int mt = 0; mt < 2; mt++) {
                uint32_t a[4];
                if (ks == 0) {
                    a[0] = aq[mt][0].x; a[1] = aq[mt][1].x;
                    a[2] = aq[mt][0].y; a[3] = aq[mt][1].y;
                } else {
                    a[0] = aq[mt][0].z; a[1] = aq[mt][1].z;
                    a[2] = aq[mt][0].w; a[3] = aq[mt][1].w;
                }
                #pragma unroll
                for (int nt = 0; nt < 8; nt++)
                    mma_tf32(acc[mt][nt], a, bf[nt]);
            }
        }

        if (has_next) {
            const int nb_ = bufA ^ 1;
            #pragma unroll
            for (int j = 0; j < 4; j++) {
                uint32_t off = am*16 + ((j ^ hA) << 2) + ah*2;
                *reinterpret_cast<uint2*>(&As[nb_][off]) =
                    make_uint2(__float_as_uint((&fa0.x)[j]), __float_as_uint((&fa1.x)[j]));
            }
            bufA = nb_;
        }

        if (kc + 2 < 16) { CP_WAIT(1); } else { CP_WAIT(0); }
        __syncthreads();
    }
}

// 3b) Expert-2 feature stage (pipelined): feat = bn_gelu(e2_k @ x[b])
__global__ void __launch_bounds__(256, 2) feat_gemm_kernel(
    const float* __restrict__ x,
    const float* __restrict__ p0, const float* __restrict__ p1,
    const float* __restrict__ p2, const float* __restrict__ p3)
{
    __shared__ __align__(16) uint32_t As[2][128*16];
    __shared__ __align__(16) uint32_t Bs[3][16][SPB];

    const int bz = blockIdx.z;
    if (g_idx[bz] != 2) return;
    const int m0 = blockIdx.y * 128;
    const int n0 = blockIdx.x * 128;

    float acc[2][8][4];
    #pragma unroll
    for (int i = 0; i < 2; i++)
        #pragma unroll
        for (int j = 0; j < 8; j++)
            #pragma unroll
            for (int t = 0; t < 4; t++) acc[i][j][t] = 0.f;

    pipe_gemm<true>(As, &Bs[0][0][0], g_wt[3], x + (size_t)bz*NCHW, m0, n0, acc);

    const int lane = threadIdx.x & 31;
    const int wid  = threadIdx.x >> 5;
    const int wm   = wid & 3;
    const int wn   = wid >> 2;
    const int gID  = lane >> 2;
    const int qid  = lane & 3;
    float* Cm = g_feat + (size_t)bz*NCHW;

    #pragma unroll
    for (int mt = 0; mt < 2; mt++) {
        #pragma unroll
        for (int half = 0; half < 2; half++) {
            const int o = m0 + wm*32 + mt*16 + half*8 + gID;
            float sc = p0[o] * rsqrtf(p3[o] + EPSV);
            float mm = p2[o];
            float bb = p1[o];
            float* cp = Cm + (size_t)o * NHW + n0 + wn*64 + qid*2;
            #pragma unroll
            for (int nt = 0; nt < 8; nt++) {
                float z0 = acc[mt][nt][half*2 + 0];
                float z1 = acc[mt][nt][half*2 + 1];
                z0 = (z0 - mm) * sc + bb; z0 = f2tf32f(gelu_exact(z0));
                z1 = (z1 - mm) * sc + bb; z1 = f2tf32f(gelu_exact(z1));
                *reinterpret_cast<float2*>(cp + nt*8) = make_float2(z0, z1);
            }
        }
    }
}

// 4) Final pointwise (pipelined): out[b] = e{idx}_pw @ feat[b] + e{idx}_pb
__global__ void __launch_bounds__(256, 2) out_gemm_kernel(
    const float* __restrict__ pb0, const float* __restrict__ pb1,
    const float* __restrict__ pb2, float* __restrict__ out)
{
    __shared__ __align__(16) uint32_t As[2][128*16];
    __shared__ __align__(16) uint32_t Bs[3][16][SPB];

    const int bz = blockIdx.z;
    const int e  = g_idx[bz];
    const float* pb = (e == 0) ? pb0 : (e == 1 ? pb1 : pb2);
    const int m0 = blockIdx.y * 128;
    const int n0 = blockIdx.x * 128;

    float acc[2][8][4];
    #pragma unroll
    for (int i = 0; i < 2; i++)
        #pragma unroll
        for (int j = 0; j < 8; j++)
            #pragma unroll
            for (int t = 0; t < 4; t++) acc[i][j][t] = 0.f;

    pipe_gemm<false>(As, &Bs[0][0][0], g_wt[e], g_feat + (size_t)bz*NCHW, m0, n0, acc);

    const int lane = threadIdx.x & 31;
    const int wid  = threadIdx.x >> 5;
    const int wm   = wid & 3;
    const int wn   = wid >> 2;
    const int gID  = lane >> 2;
    const int qid  = lane & 3;
    float* Cm = out + (size_t)bz*NCHW;

    #pragma unroll
    for (int mt = 0; mt < 2; mt++) {
        #pragma unroll
        for (int half = 0; half < 2; half++) {
            const int o = m0 + wm*32 + mt*16 + half*8 + gID;
            const float bb = pb[o];
            float* cp = Cm + (size_t)o * NHW + n0 + wn*64 + qid*2;
            #pragma unroll
            for (int nt = 0; nt < 8; nt++) {
                *reinterpret_cast<float2*>(cp + nt*8) =
                    make_float2(acc[mt][nt][half*2 + 0] + bb,
                                acc[mt][nt][half*2 + 1] + bb);
            }
        }
    }
}

// ---------------------------------------------------------------------------
extern "C" void kernel_launch(void* const* d_in, const int* in_sizes, int n_in,
                              void* d_out, int out_size) {
    const float* x    = (const float*)d_in[0];
    const float* rw   = (const float*)d_in[1];
    const float* rb   = (const float*)d_in[2];
    const float* e0_k = (const float*)d_in[3];
    const float* e0_g = (const float*)d_in[4];
    const float* e0_b = (const float*)d_in[5];
    const float* e0_m = (const float*)d_in[6];
    const float* e0_v = (const float*)d_in[7];
    const float* e0_pw= (const float*)d_in[8];
    const float* e0_pb= (const float*)d_in[9];
    const float* e1_k = (const float*)d_in[10];
    const float* e1_g = (const float*)d_in[11];
    const float* e1_b = (const float*)d_in[12];
    const float* e1_m = (const float*)d_in[13];
    const float* e1_v = (const float*)d_in[14];
    const float* e1_pw= (const float*)d_in[15];
    const float* e1_pb= (const float*)d_in[16];
    const float* e2_k = (const float*)d_in[17];
    const float* e2_g = (const float*)d_in[18];
    const float* e2_b = (const float*)d_in[19];
    const float* e2_m = (const float*)d_in[20];
    const float* e2_v = (const float*)d_in[21];
    const float* e2_pw= (const float*)d_in[22];
    const float* e2_pb= (const float*)d_in[23];
    float* out = (float*)d_out;

    pool_prep_kernel<<<NB*NC + 1024, 256>>>(x, e0_pw, e1_pw, e2_pw, e2_k);
    route_kernel<<<1, 32>>>(rw, rb);

    dwconv_bn_gelu_kernel<<<dim3(NC, NB), 256>>>(
        x, e0_k, e0_g, e0_b, e0_m, e0_v,
           e1_k, e1_g, e1_b, e1_m, e1_v);

    dim3 ggrid(NHW/128, NC/128, NB);   // (32, 2, 32)
    feat_gemm_kernel<<<ggrid, 256>>>(x, e2_g, e2_b, e2_m, e2_v);
    out_gemm_kernel<<<ggrid, 256>>>(e0_pb, e1_pb, e2_pb, out);
}

// round 13
// speedup vs baseline: 1.2610x; 1.0127x over previous
#include <cuda_runtime.h>
#include <math.h>
#include <stdint.h>

#define NB 32
#define NC 256
#define NH 64
#define NW 64
#define NHW 4096
#define NCHW (NC*NHW)
#define EPSV 1e-5f

// Scratch (allocation-free rule: __device__ globals)
__device__ float g_pooled[NB*NC];
__device__ int   g_idx[NB];
// g_feat layout: per (b,c) plane of 4096 floats, stored n-PERMUTED:
//   idx = (n & ~31) | ((n & 7) << 2) | ((n >> 3) & 3)
// values are tf32-rounded. Written by dwconv + feat epilogues, read by out_gemm.
__device__ float g_feat[(size_t)NB*NCHW];
__device__ float g_wt[4][NC*NC];            // tf32-rounded weights: e0_pw,e1_pw,e2_pw,e2_k

__device__ __forceinline__ uint32_t f2tf32(float f) {
    uint32_t r;
    asm("cvt.rna.tf32.f32 %0, %1;" : "=r"(r) : "f"(f));
    return r;
}
__device__ __forceinline__ uint32_t u2tf32(uint32_t u) {
    uint32_t r;
    asm("cvt.rna.tf32.f32 %0, %1;" : "=r"(r) : "f"(__uint_as_float(u)));
    return r;
}
__device__ __forceinline__ float f2tf32f(float f) { return __uint_as_float(f2tf32(f)); }

__device__ __forceinline__ float gelu_exact(float z) {
    return 0.5f * z * (1.0f + erff(z * 0.7071067811865475f));
}

__device__ __forceinline__ uint32_t smem_addr_u32(const void* p) {
    return (uint32_t)__cvta_generic_to_shared(p);
}
__device__ __forceinline__ void cp_async16(uint32_t dst, const void* src) {
    asm volatile("cp.async.ca.shared.global [%0], [%1], 16;" :: "r"(dst), "l"(src));
}
#define CP_COMMIT() asm volatile("cp.async.commit_group;")
#define CP_WAIT(n)  asm volatile("cp.async.wait_group %0;" :: "n"(n))

// ---------------------------------------------------------------------------
// 1) Fused: global average pool + weight pre-convert
// ---------------------------------------------------------------------------
__global__ void pool_prep_kernel(const float* __restrict__ x,
                                 const float* __restrict__ w0, const float* __restrict__ w1,
                                 const float* __restrict__ w2, const float* __restrict__ k2) {
    if (blockIdx.x < NB*NC) {
        int bc = blockIdx.x;
        const float4* p = reinterpret_cast<const float4*>(x + (size_t)bc * NHW);
        float s = 0.f;
        for (int i = threadIdx.x; i < NHW/4; i += 256) {
            float4 v = p[i];
            s += (v.x + v.y) + (v.z + v.w);
        }
        __shared__ float red[8];
        #pragma unroll
        for (int o = 16; o > 0; o >>= 1) s += __shfl_down_sync(0xffffffffu, s, o);
        if ((threadIdx.x & 31) == 0) red[threadIdx.x >> 5] = s;
        __syncthreads();
        if (threadIdx.x < 8) {
            float t = red[threadIdx.x];
            #pragma unroll
            for (int o = 4; o > 0; o >>= 1) t += __shfl_down_sync(0xffu, t, o);
            if (threadIdx.x == 0) g_pooled[bc] = t * (1.0f / NHW);
        }
    } else {
        int i = (blockIdx.x - NB*NC) * 256 + threadIdx.x;
        int m = i >> 16;
        int o = i & 0xFFFF;
        const float* src = (m == 0) ? w0 : (m == 1) ? w1 : (m == 2) ? w2 : k2;
        g_wt[m][o] = f2tf32f(src[o]);
    }
}

// ---------------------------------------------------------------------------
// 2) Router
// ---------------------------------------------------------------------------
__global__ void route_kernel(const float* __restrict__ rw, const float* __restrict__ rb) {
    int b = threadIdx.x;
    if (b >= NB) return;
    float best = -1e30f; int bi = 0;
    #pragma unroll
    for (int j = 0; j < 3; j++) {
        float s = rb[j];
        const float* w = rw + j*NC;
        const float* p = g_pooled + b*NC;
        for (int c = 0; c < NC; c++) s = fmaf(p[c], w[c], s);
        if (s > best) { best = s; bi = j; }
    }
    g_idx[b] = bi;
}

// ---------------------------------------------------------------------------
// 3a) Depthwise 3x3 conv + BN + exact GELU; output PERMUTED tf32
// ---------------------------------------------------------------------------
#define SMC 70

template<int D>
__device__ __forceinline__ void dwconv_plane(
    float (*sm)[SMC], const float* __restrict__ xp, const float* __restrict__ kw9,
    float scale, float mm, float bb, float* __restrict__ outp)
{
    const int tid = threadIdx.x;

    for (int i = tid; i < 272; i += 256) {
        int r = i / 68, c = i % 68;
        sm[(r < 2) ? r : r + 64][c] = 0.f;
    }
    {
        int r = 2 + (tid >> 2);
        int c = tid & 3;
        sm[r][(c < 2) ? c : c + 64] = 0.f;
    }

    #pragma unroll
    for (int i = 0; i < 4; i++) {
        int idx = tid + i*256;
        int y = idx >> 4, x4 = (idx & 15) * 4;
        float4 v = reinterpret_cast<const float4*>(xp)[idx];
        sm[y+2][x4+2+0] = v.x;
        sm[y+2][x4+2+1] = v.y;
        sm[y+2][x4+2+2] = v.z;
        sm[y+2][x4+2+3] = v.w;
    }
    __syncthreads();

    const int y  = tid >> 2;
    const int x0 = (tid & 3) * 16;

    float acc[16];
    #pragma unroll
    for (int j = 0; j < 16; j++) acc[j] = 0.f;

    #pragma unroll
    for (int dy = 0; dy < 3; dy++) {
        const float* row = &sm[y + 2 + (dy-1)*D][x0 + 2 - D];
        const float w0 = kw9[dy*3 + 0];
        const float w1 = kw9[dy*3 + 1];
        const float w2 = kw9[dy*3 + 2];
        float v[16 + 2*D];
        #pragma unroll
        for (int j = 0; j < 16 + 2*D; j++) v[j] = row[j];
        #pragma unroll
        for (int j = 0; j < 16; j++)
            acc[j] = fmaf(w0, v[j], fmaf(w1, v[j+D], fmaf(w2, v[j+2*D], acc[j])));
    }

    // permuted store: pixel n = y*64 + x0 + j (j<8) -> word 4j + q0 of its
    // 32-group; n = .. + j + 8 -> word 4j + q0 + 1. q0 = (x0>>3)&3 (even).
    float* base = outp + y*NW + (x0 & 32) + ((x0 >> 3) & 3);
    #pragma unroll
    for (int j = 0; j < 8; j++) {
        float z0 = (acc[j]     - mm) * scale + bb;
        float z1 = (acc[j + 8] - mm) * scale + bb;
        z0 = f2tf32f(gelu_exact(z0));
        z1 = f2tf32f(gelu_exact(z1));
        *reinterpret_cast<float2*>(base + 4*j) = make_float2(z0, z1);
    }
}

__global__ void __launch_bounds__(256) dwconv_bn_gelu_kernel(
    const float* __restrict__ x,
    const float* __restrict__ k0, const float* __restrict__ g0, const float* __restrict__ b0,
    const float* __restrict__ m0, const float* __restrict__ v0,
    const float* __restrict__ k1, const float* __restrict__ g1, const float* __restrict__ b1,
    const float* __restrict__ m1, const float* __restrict__ v1)
{
    __shared__ float sm[68][SMC];
    const int b = blockIdx.y;
    const int e = g_idx[b];
    if (e == 2) return;
    const int c = blockIdx.x;

    const float gg = (e == 0 ? g0[c] : g1[c]);
    const float vv = (e == 0 ? v0[c] : v1[c]);
    const float mm = (e == 0 ? m0[c] : m1[c]);
    const float bb = (e == 0 ? b0[c] : b1[c]);
    const float scale = gg * rsqrtf(vv + EPSV);
    const float* kw = (e == 0 ? k0 : k1) + c * 9;
    const float* xp = x + ((size_t)b*NC + c) * NHW;
    float* outp = g_feat + ((size_t)b*NC + c) * NHW;

    if (e == 0) dwconv_plane<1>(sm, xp, kw, scale, mm, bb, outp);
    else        dwconv_plane<2>(sm, xp, kw, scale, mm, bb, outp);
}

// ---------------------------------------------------------------------------
// mma.sync tf32 primitive
// ---------------------------------------------------------------------------
__device__ __forceinline__ void mma_tf32(float c[4], const uint32_t a[4], const uint32_t b[2]) {
    asm volatile(
        "mma.sync.aligned.m16n8k8.row.col.f32.tf32.tf32.f32 "
        "{%0,%1,%2,%3}, {%4,%5,%6,%7}, {%8,%9}, {%0,%1,%2,%3};"
        : "+f"(c[0]), "+f"(c[1]), "+f"(c[2]), "+f"(c[3])
        : "r"(a[0]), "r"(a[1]), "r"(a[2]), "r"(a[3]),
          "r"(b[0]), "r"(b[1]));
}

#define SPB 136

// ---------------------------------------------------------------------------
// 3b) feat GEMM: feat[b] = bn_gelu(e2_k @ x[b]) for idx==2.
// cp.async raw fp32 (2 stages) -> in-smem RNA convert one chunk ahead
// (2 tf32 stages, natural n order) -> LDS.32 fragments (no per-frag CVT).
// Epilogue writes g_feat PERMUTED.
// Dynamic smem: As[2][2048] | Braw[2][16*SPB] | Bconv[2][16*SPB] words.
// ---------------------------------------------------------------------------
#define FEAT_SMEM ((4096 + 2*16*SPB + 2*16*SPB) * 4)   // 51200 bytes

__global__ void __launch_bounds__(256, 2) feat_gemm_kernel(
    const float* __restrict__ x,
    const float* __restrict__ p0, const float* __restrict__ p1,
    const float* __restrict__ p2, const float* __restrict__ p3)
{
    extern __shared__ uint32_t dynw[];
    uint32_t* Asw   = dynw;                    // [2][2048]
    uint32_t* Braw  = dynw + 4096;             // [2][16*SPB]
    uint32_t* Bconv = dynw + 4096 + 2*16*SPB;  // [2][16*SPB]

    const int bz = blockIdx.z;
    if (g_idx[bz] != 2) return;
    const float* A  = g_wt[3];
    const float* Bm = x + (size_t)bz*NCHW;
    float* Cm = g_feat + (size_t)bz*NCHW;

    const int tid  = threadIdx.x;
    const int lane = tid & 31;
    const int wid  = tid >> 5;
    const int wm   = wid & 3;
    const int wn   = wid >> 2;
    const int gID  = lane >> 2;
    const int qid  = lane & 3;
    const int m0   = blockIdx.y * 128;
    const int n0   = blockIdx.x * 128;

    const int am = tid >> 1;
    const int ah = tid & 1;
    const uint32_t hA = (uint32_t)((am ^ (am >> 2)) & 3);
    const float* aSrc = A + (size_t)(m0 + am) * NC + ah*8;

    const int bkA = tid >> 5;
    const int bj  = tid & 31;
    const uint32_t rawBase = smem_addr_u32(Braw);
    const uint32_t rDst0 = rawBase + (uint32_t)bkA       * (SPB*4) + (uint32_t)bj * 16;
    const uint32_t rDst1 = rawBase + (uint32_t)(bkA + 8) * (SPB*4) + (uint32_t)bj * 16;
    const float* bSrc = Bm + (size_t)bkA * NHW + n0 + bj*4;
    const uint32_t stageBytes = 16 * SPB * 4;

    float acc[2][8][4];
    #pragma unroll
    for (int i = 0; i < 2; i++)
        #pragma unroll
        for (int j = 0; j < 8; j++)
            #pragma unroll
            for (int t = 0; t < 4; t++) acc[i][j][t] = 0.f;

    // prologue: cp chunk0->raw0, chunk1->raw1; stage A0; convert chunk0
    cp_async16(rDst0, bSrc);
    cp_async16(rDst1, bSrc + (size_t)8 * NHW);
    CP_COMMIT();
    cp_async16(rDst0 + stageBytes, bSrc + (size_t)16 * NHW);
    cp_async16(rDst1 + stageBytes, bSrc + (size_t)24 * NHW);
    CP_COMMIT();
    {
        float4 fa0 = *reinterpret_cast<const float4*>(aSrc);
        float4 fa1 = *reinterpret_cast<const float4*>(aSrc + 4);
        #pragma unroll
        for (int j = 0; j < 4; j++) {
            uint32_t off = am*16 + ((j ^ hA) << 2) + ah*2;
            *reinterpret_cast<uint2*>(&Asw[off]) =
                make_uint2(__float_as_uint((&fa0.x)[j]), __float_as_uint((&fa1.x)[j]));
        }
    }
    CP_WAIT(1);
    {   // convert chunk0: raw[0] -> conv[0] (each thread converts its own cp'd data)
        uint4 v0 = *reinterpret_cast<const uint4*>(&Braw[bkA*SPB + bj*4]);
        uint4 v1 = *reinterpret_cast<const uint4*>(&Braw[(bkA+8)*SPB + bj*4]);
        uint4 r0 = make_uint4(u2tf32(v0.x), u2tf32(v0.y), u2tf32(v0.z), u2tf32(v0.w));
        uint4 r1 = make_uint4(u2tf32(v1.x), u2tf32(v1.y), u2tf32(v1.z), u2tf32(v1.w));
        *reinterpret_cast<uint4*>(&Bconv[bkA*SPB + bj*4])     = r0;
        *reinterpret_cast<uint4*>(&Bconv[(bkA+8)*SPB + bj*4]) = r1;
    }
    __syncthreads();

    int bufA = 0;
    for (int kc = 0; kc < 16; kc++) {
        const uint32_t* BsStage = Bconv + (kc & 1) * (16*SPB);

        if (kc + 2 < 16) {     // cp chunk kc+2 into raw[kc&1] (its old data converted last iter)
            const uint32_t so = (uint32_t)(kc & 1) * stageBytes;
            const float* s = bSrc + (size_t)(kc + 2) * 16 * NHW;
            cp_async16(rDst0 + so, s);
            cp_async16(rDst1 + so, s + (size_t)8 * NHW);
            CP_COMMIT();
        }
        float4 fa0, fa1;
        const bool has_next = (kc + 1) < 16;
        if (has_next) {
            const int kn = (kc + 1) * 16;
            fa0 = *reinterpret_cast<const float4*>(aSrc + kn);
            fa1 = *reinterpret_cast<const float4*>(aSrc + kn + 4);
        }

        uint4 aq[2][2];
        #pragma unroll
        for (int mt = 0; mt < 2; mt++)
            #pragma unroll
            for (int mh = 0; mh < 2; mh++) {
                int m = wm*32 + mt*16 + mh*8 + gID;
                uint32_t off = m*16 + (((qid ^ ((m ^ (m >> 2)) & 3))) << 2);
                aq[mt][mh] = *reinterpret_cast<const uint4*>(&Asw[bufA*2048 + off]);
            }

        #pragma unroll
        for (int ks = 0; ks < 2; ks++) {
            uint32_t bf[8][2];
            #pragma unroll
            for (int nt = 0; nt < 8; nt++) {
                int n = wn*64 + nt*8 + gID;
                bf[nt][0] = BsStage[(ks*8 + qid)     * SPB + n];
                bf[nt][1] = BsStage[(ks*8 + qid + 4) * SPB + n];
            }
            #pragma unroll
            for (int mt = 0; mt < 2; mt++) {
                uint32_t a[4];
                if (ks == 0) {
                    a[0] = aq[mt][0].x; a[1] = aq[mt][1].x;
                    a[2] = aq[mt][0].y; a[3] = aq[mt][1].y;
                } else {
                    a[0] = aq[mt][0].z; a[1] = aq[mt][1].z;
                    a[2] = aq[mt][0].w; a[3] = aq[mt][1].w;
                }
                #pragma unroll
                for (int nt = 0; nt < 8; nt++)
                    mma_tf32(acc[mt][nt], a, bf[nt]);
            }
        }

        if (has_next) {
            const int nb_ = bufA ^ 1;
            #pragma unroll
            for (int j = 0; j < 4; j++) {
                uint32_t off = am*16 + ((j ^ hA) << 2) + ah*2;
                *reinterpret_cast<uint2*>(&Asw[nb_*2048 + off]) =
                    make_uint2(__float_as_uint((&fa0.x)[j]), __float_as_uint((&fa1.x)[j]));
            }
            bufA = nb_;
        }

        if (kc + 2 < 16) { CP_WAIT(1); } else { CP_WAIT(0); }
        if (has_next) {   // convert chunk kc+1: raw[(kc+1)&1] -> conv[(kc+1)&1]
            const int s = (kc + 1) & 1;
            uint4 v0 = *reinterpret_cast<const uint4*>(&Braw[s*(16*SPB) + bkA*SPB + bj*4]);
            uint4 v1 = *reinterpret_cast<const uint4*>(&Braw[s*(16*SPB) + (bkA+8)*SPB + bj*4]);
            uint4 r0 = make_uint4(u2tf32(v0.x), u2tf32(v0.y), u2tf32(v0.z), u2tf32(v0.w));
            uint4 r1 = make_uint4(u2tf32(v1.x), u2tf32(v1.y), u2tf32(v1.z), u2tf32(v1.w));
            *reinterpret_cast<uint4*>(&Bconv[s*(16*SPB) + bkA*SPB + bj*4])     = r0;
            *reinterpret_cast<uint4*>(&Bconv[s*(16*SPB) + (bkA+8)*SPB + bj*4]) = r1;
        }
        __syncthreads();
    }

    // epilogue: BN+GELU, tf32 round, PERMUTED store.
    // acc[mt][nt] covers orig n = n0 + wn*64 + nt*8 + qid*2 + {0,1}.
    // perm: group32 = n0+wn*64+(nt>=4?32:0); z0 -> word 8*qid + (nt&3); z1 -> +4.
    #pragma unroll
    for (int mt = 0; mt < 2; mt++) {
        #pragma unroll
        for (int half = 0; half < 2; half++) {
            const int o = m0 + wm*32 + mt*16 + half*8 + gID;
            float sc = p0[o] * rsqrtf(p3[o] + EPSV);
            float mm = p2[o];
            float bb = p1[o];
            float* gbase = Cm + (size_t)o * NHW + n0 + wn*64;
            #pragma unroll
            for (int ntg = 0; ntg < 2; ntg++) {
                float z0[4], z1[4];
                #pragma unroll
                for (int c = 0; c < 4; c++) {
                    float a0 = acc[mt][ntg*4 + c][half*2 + 0];
                    float a1 = acc[mt][ntg*4 + c][half*2 + 1];
                    a0 = (a0 - mm) * sc + bb; z0[c] = f2tf32f(gelu_exact(a0));
                    a1 = (a1 - mm) * sc + bb; z1[c] = f2tf32f(gelu_exact(a1));
                }
                float* gp = gbase + ntg*32 + 8*qid;
                *reinterpret_cast<float4*>(gp)     = make_float4(z0[0], z0[1], z0[2], z0[3]);
                *reinterpret_cast<float4*>(gp + 4) = make_float4(z1[0], z1[1], z1[2], z1[3]);
            }
        }
    }
}

// ---------------------------------------------------------------------------
// 4) out GEMM: B (g_feat) already tf32 + PERMUTED -> cp.async 3 stages,
//    LDS.128 B fragments (R6 mapping: tile nt=bl*4+c covers col bl*32+c*8),
//    natural epilogue (identical arithmetic to before).
// ---------------------------------------------------------------------------
__global__ void __launch_bounds__(256, 2) out_gemm_kernel(
    const float* __restrict__ pb0, const float* __restrict__ pb1,
    const float* __restrict__ pb2, float* __restrict__ out)
{
    __shared__ __align__(16) uint32_t As[2][128*16];
    __shared__ __align__(16) uint32_t Bs[3][16][SPB];

    const int bz = blockIdx.z;
    const int e  = g_idx[bz];
    const float* A  = g_wt[e];
    const float* pb = (e == 0) ? pb0 : (e == 1 ? pb1 : pb2);
    const float* Bm = g_feat + (size_t)bz*NCHW;
    float* Cm = out + (size_t)bz*NCHW;

    const int tid  = threadIdx.x;
    const int lane = tid & 31;
    const int wid  = tid >> 5;
    const int wm   = wid & 3;
    const int wn   = wid >> 2;
    const int gID  = lane >> 2;
    const int qid  = lane & 3;
    const int m0   = blockIdx.y * 128;
    const int n0   = blockIdx.x * 128;

    const int am = tid >> 1;
    const int ah = tid & 1;
    const uint32_t hA = (uint32_t)((am ^ (am >> 2)) & 3);
    const float* aSrc = A + (size_t)(m0 + am) * NC + ah*8;

    const int bkA = tid >> 5;
    const int bj  = tid & 31;
    const uint32_t bs0 = smem_addr_u32(&Bs[0][0][0]);
    const uint32_t bDst0 = bs0 + (uint32_t)bkA       * (SPB*4) + (uint32_t)bj * 16;
    const uint32_t bDst1 = bs0 + (uint32_t)(bkA + 8) * (SPB*4) + (uint32_t)bj * 16;
    const float* bSrc = Bm + (size_t)bkA * NHW + n0 + bj*4;
    const uint32_t stageBytes = 16 * SPB * 4;

    float acc[2][8][4];
    #pragma unroll
    for (int i = 0; i < 2; i++)
        #pragma unroll
        for (int j = 0; j < 8; j++)
            #pragma unroll
            for (int t = 0; t < 4; t++) acc[i][j][t] = 0.f;

    cp_async16(bDst0, bSrc);
    cp_async16(bDst1, bSrc + (size_t)8 * NHW);
    CP_COMMIT();
    cp_async16(bDst0 + stageBytes, bSrc + (size_t)16 * NHW);
    cp_async16(bDst1 + stageBytes, bSrc + (size_t)24 * NHW);
    CP_COMMIT();
    {
        float4 fa0 = *reinterpret_cast<const float4*>(aSrc);
        float4 fa1 = *reinterpret_cast<const float4*>(aSrc + 4);
        #pragma unroll
        for (int j = 0; j < 4; j++) {
            uint32_t off = am*16 + ((j ^ hA) << 2) + ah*2;
            *reinterpret_cast<uint2*>(&As[0][off]) =
                make_uint2(__float_as_uint((&fa0.x)[j]), __float_as_uint((&fa1.x)[j]));
        }
    }
    CP_WAIT(1);
    __syncthreads();

    int bufA = 0;
    for (int kc = 0; kc < 16; kc++) {
        const uint32_t (*BsStage)[SPB] = Bs[kc % 3];

        if (kc + 2 < 16) {
            const uint32_t so = (uint32_t)((kc + 2) % 3) * stageBytes;
            const float* s = bSrc + (size_t)(kc + 2) * 16 * NHW;
            cp_async16(bDst0 + so, s);
            cp_async16(bDst1 + so, s + (size_t)8 * NHW);
            CP_COMMIT();
        }
        float4 fa0, fa1;
        const bool has_next = (kc + 1) < 16;
        if (has_next) {
            const int kn = (kc + 1) * 16;
            fa0 = *reinterpret_cast<const float4*>(aSrc + kn);
            fa1 = *reinterpret_cast<const float4*>(aSrc + kn + 4);
        }

        uint4 aq[2][2];
        #pragma unroll
        for (int mt = 0; mt < 2; mt++)
            #pragma unroll
            for (int mh = 0; mh < 2; mh++) {
                int m = wm*32 + mt*16 + mh*8 + gID;
                uint32_t off = m*16 + (((qid ^ ((m ^ (m >> 2)) & 3))) << 2);
                aq[mt][mh] = *reinterpret_cast<const uint4*>(&As[bufA][off]);
            }

        #pragma unroll
        for (int ks = 0; ks < 2; ks++) {
            // LDS.128 B fragments (permuted layout): bq[kh][bl] covers 4 tiles
            uint4 bq[2][2];
            #pragma unroll
            for (int kh = 0; kh < 2; kh++)
                #pragma unroll
                for (int bl = 0; bl < 2; bl++) {
                    int krow = ks*8 + kh*4 + qid;
                    int ncol = (wn*2 + bl)*32 + gID*4;
                    bq[kh][bl] = *reinterpret_cast<const uint4*>(&BsStage[krow][ncol]);
                }

            #pragma unroll
            for (int mt = 0; mt < 2; mt++) {
                uint32_t a[4];
                if (ks == 0) {
                    a[0] = aq[mt][0].x; a[1] = aq[mt][1].x;
                    a[2] = aq[mt][0].y; a[3] = aq[mt][1].y;
                } else {
                    a[0] = aq[mt][0].z; a[1] = aq[mt][1].z;
                    a[2] = aq[mt][0].w; a[3] = aq[mt][1].w;
                }
                #pragma unroll
                for (int bl = 0; bl < 2; bl++) {
                    #pragma unroll
                    for (int c = 0; c < 4; c++) {
                        uint32_t b[2];
                        b[0] = (&bq[0][bl].x)[c];
                        b[1] = (&bq[1][bl].x)[c];
                        mma_tf32(acc[mt][bl*4 + c], a, b);
                    }
                }
            }
        }

        if (has_next) {
            const int nb_ = bufA ^ 1;
            #pragma unroll
            for (int j = 0; j < 4; j++) {
                uint32_t off = am*16 + ((j ^ hA) << 2) + ah*2;
                *reinterpret_cast<uint2*>(&As[nb_][off]) =
                    make_uint2(__float_as_uint((&fa0.x)[j]), __float_as_uint((&fa1.x)[j]));
            }
            bufA = nb_;
        }

        if (kc + 2 < 16) { CP_WAIT(1); } else { CP_WAIT(0); }
        __syncthreads();
    }

    // epilogue: tile nt=bl*4+c covers col nt*8 (== bl*32+c*8) — natural writes
    #pragma unroll
    for (int mt = 0; mt < 2; mt++) {
        #pragma unroll
        for (int half = 0; half < 2; half++) {
            const int o = m0 + wm*32 + mt*16 + half*8 + gID;
            const float bb = pb[o];
            float* cp = Cm + (size_t)o * NHW + n0 + wn*64 + qid*2;
            #pragma unroll
            for (int nt = 0; nt < 8; nt++) {
                *reinterpret_cast<float2*>(cp + nt*8) =
                    make_float2(acc[mt][nt][half*2 + 0] + bb,
                                acc[mt][nt][half*2 + 1] + bb);
            }
        }
    }
}

// ---------------------------------------------------------------------------
extern "C" void kernel_launch(void* const* d_in, const int* in_sizes, int n_in,
                              void* d_out, int out_size) {
    const float* x    = (const float*)d_in[0];
    const float* rw   = (const float*)d_in[1];
    const float* rb   = (const float*)d_in[2];
    const float* e0_k = (const float*)d_in[3];
    const float* e0_g = (const float*)d_in[4];
    const float* e0_b = (const float*)d_in[5];
    const float* e0_m = (const float*)d_in[6];
    const float* e0_v = (const float*)d_in[7];
    const float* e0_pw= (const float*)d_in[8];
    const float* e0_pb= (const float*)d_in[9];
    const float* e1_k = (const float*)d_in[10];
    const float* e1_g = (const float*)d_in[11];
    const float* e1_b = (const float*)d_in[12];
    const float* e1_m = (const float*)d_in[13];
    const float* e1_v = (const float*)d_in[14];
    const float* e1_pw= (const float*)d_in[15];
    const float* e1_pb= (const float*)d_in[16];
    const float* e2_k = (const float*)d_in[17];
    const float* e2_g = (const float*)d_in[18];
    const float* e2_b = (const float*)d_in[19];
    const float* e2_m = (const float*)d_in[20];
    const float* e2_v = (const float*)d_in[21];
    const float* e2_pw= (const float*)d_in[22];
    const float* e2_pb= (const float*)d_in[23];
    float* out = (float*)d_out;

    cudaFuncSetAttribute(feat_gemm_kernel,
                         cudaFuncAttributeMaxDynamicSharedMemorySize, FEAT_SMEM);

    pool_prep_kernel<<<NB*NC + 1024, 256>>>(x, e0_pw, e1_pw, e2_pw, e2_k);
    route_kernel<<<1, 32>>>(rw, rb);

    dwconv_bn_gelu_kernel<<<dim3(NC, NB), 256>>>(
        x, e0_k, e0_g, e0_b, e0_m, e0_v,
           e1_k, e1_g, e1_b, e1_m, e1_v);

    dim3 ggrid(NHW/128, NC/128, NB);   // (32, 2, 32)
    feat_gemm_kernel<<<ggrid, 256, FEAT_SMEM>>>(x, e2_g, e2_b, e2_m, e2_v);
    out_gemm_kernel<<<ggrid, 256>>>(e0_pb, e1_pb, e2_pb, out);
}

// round 14
// speedup vs baseline: 1.7664x; 1.4008x over previous
#include <cuda_runtime.h>
#include <cuda_fp16.h>
#include <math.h>
#include <stdint.h>

#define NB 32
#define NC 256
#define NH 64
#define NW 64
#define NHW 4096
#define NCHW (NC*NHW)
#define EPSV 1e-5f

// Scratch (allocation-free rule: __device__ globals)
__device__ float  g_pooled[NB*NC];
__device__ int    g_idx[NB];
__device__ __half g_x16[(size_t)NB*NCHW];     // fp16 copy of x (written by pool)
__device__ __half g_feat16[(size_t)NB*NCHW];  // fp16 feature scratch, natural [c][n]
__device__ __half g_wt16[4][NC*NC];           // fp16 weights: e0_pw,e1_pw,e2_pw,e2_k

__device__ __forceinline__ float gelu_exact(float z) {
    return 0.5f * z * (1.0f + erff(z * 0.7071067811865475f));
}
__device__ __forceinline__ uint32_t smem_addr_u32(const void* p) {
    return (uint32_t)__cvta_generic_to_shared(p);
}
__device__ __forceinline__ void cp_async16(uint32_t dst, const void* src) {
    asm volatile("cp.async.ca.shared.global [%0], [%1], 16;" :: "r"(dst), "l"(src));
}
#define CP_COMMIT() asm volatile("cp.async.commit_group;")
#define CP_WAIT(n)  asm volatile("cp.async.wait_group %0;" :: "n"(n))

__device__ __forceinline__ uint32_t h2u(__half2 h) {
    return *reinterpret_cast<uint32_t*>(&h);
}

// ---------------------------------------------------------------------------
// 1) Fused: global average pool (+ fp16 copy of x) + weight pre-convert
// ---------------------------------------------------------------------------
__global__ void pool_prep_kernel(const float* __restrict__ x,
                                 const float* __restrict__ w0, const float* __restrict__ w1,
                                 const float* __restrict__ w2, const float* __restrict__ k2) {
    if (blockIdx.x < NB*NC) {
        int bc = blockIdx.x;
        const float4* p = reinterpret_cast<const float4*>(x + (size_t)bc * NHW);
        uint2* o16 = reinterpret_cast<uint2*>(g_x16 + (size_t)bc * NHW);
        float s = 0.f;
        for (int i = threadIdx.x; i < NHW/4; i += 256) {
            float4 v = p[i];
            s += (v.x + v.y) + (v.z + v.w);
            o16[i] = make_uint2(h2u(__floats2half2_rn(v.x, v.y)),
                                h2u(__floats2half2_rn(v.z, v.w)));
        }
        __shared__ float red[8];
        #pragma unroll
        for (int o = 16; o > 0; o >>= 1) s += __shfl_down_sync(0xffffffffu, s, o);
        if ((threadIdx.x & 31) == 0) red[threadIdx.x >> 5] = s;
        __syncthreads();
        if (threadIdx.x < 8) {
            float t = red[threadIdx.x];
            #pragma unroll
            for (int o = 4; o > 0; o >>= 1) t += __shfl_down_sync(0xffu, t, o);
            if (threadIdx.x == 0) g_pooled[bc] = t * (1.0f / NHW);
        }
    } else {
        int i = (blockIdx.x - NB*NC) * 256 + threadIdx.x;
        int m = i >> 16;
        int o = i & 0xFFFF;
        const float* src = (m == 0) ? w0 : (m == 1) ? w1 : (m == 2) ? w2 : k2;
        g_wt16[m][o] = __float2half_rn(src[o]);
    }
}

// ---------------------------------------------------------------------------
// 2) Router
// ---------------------------------------------------------------------------
__global__ void route_kernel(const float* __restrict__ rw, const float* __restrict__ rb) {
    int b = threadIdx.x;
    if (b >= NB) return;
    float best = -1e30f; int bi = 0;
    #pragma unroll
    for (int j = 0; j < 3; j++) {
        float s = rb[j];
        const float* w = rw + j*NC;
        const float* p = g_pooled + b*NC;
        for (int c = 0; c < NC; c++) s = fmaf(p[c], w[c], s);
        if (s > best) { best = s; bi = j; }
    }
    g_idx[b] = bi;
}

// ---------------------------------------------------------------------------
// 3a) Depthwise 3x3 conv + BN + exact GELU (R9-proven); output fp16 natural
// ---------------------------------------------------------------------------
#define SMC 70

template<int D>
__device__ __forceinline__ void dwconv_plane(
    float (*sm)[SMC], const float* __restrict__ xp, const float* __restrict__ kw9,
    float scale, float mm, float bb, __half* __restrict__ outp)
{
    const int tid = threadIdx.x;

    for (int i = tid; i < 272; i += 256) {
        int r = i / 68, c = i % 68;
        sm[(r < 2) ? r : r + 64][c] = 0.f;
    }
    {
        int r = 2 + (tid >> 2);
        int c = tid & 3;
        sm[r][(c < 2) ? c : c + 64] = 0.f;
    }

    #pragma unroll
    for (int i = 0; i < 4; i++) {
        int idx = tid + i*256;
        int y = idx >> 4, x4 = (idx & 15) * 4;
        float4 v = reinterpret_cast<const float4*>(xp)[idx];
        sm[y+2][x4+2+0] = v.x;
        sm[y+2][x4+2+1] = v.y;
        sm[y+2][x4+2+2] = v.z;
        sm[y+2][x4+2+3] = v.w;
    }
    __syncthreads();

    const int y  = tid >> 2;
    const int x0 = (tid & 3) * 16;

    float acc[16];
    #pragma unroll
    for (int j = 0; j < 16; j++) acc[j] = 0.f;

    #pragma unroll
    for (int dy = 0; dy < 3; dy++) {
        const float* row = &sm[y + 2 + (dy-1)*D][x0 + 2 - D];
        const float w0 = kw9[dy*3 + 0];
        const float w1 = kw9[dy*3 + 1];
        const float w2 = kw9[dy*3 + 2];
        float v[16 + 2*D];
        #pragma unroll
        for (int j = 0; j < 16 + 2*D; j++) v[j] = row[j];
        #pragma unroll
        for (int j = 0; j < 16; j++)
            acc[j] = fmaf(w0, v[j], fmaf(w1, v[j+D], fmaf(w2, v[j+2*D], acc[j])));
    }

    uint32_t pk[8];
    #pragma unroll
    for (int jj = 0; jj < 8; jj++) {
        float z0 = (acc[2*jj]   - mm) * scale + bb;
        float z1 = (acc[2*jj+1] - mm) * scale + bb;
        pk[jj] = h2u(__floats2half2_rn(gelu_exact(z0), gelu_exact(z1)));
    }
    __half* op = outp + y*NW + x0;
    *reinterpret_cast<uint4*>(op)     = make_uint4(pk[0], pk[1], pk[2], pk[3]);
    *reinterpret_cast<uint4*>(op + 8) = make_uint4(pk[4], pk[5], pk[6], pk[7]);
}

__global__ void __launch_bounds__(256) dwconv_bn_gelu_kernel(
    const float* __restrict__ x,
    const float* __restrict__ k0, const float* __restrict__ g0, const float* __restrict__ b0,
    const float* __restrict__ m0, const float* __restrict__ v0,
    const float* __restrict__ k1, const float* __restrict__ g1, const float* __restrict__ b1,
    const float* __restrict__ m1, const float* __restrict__ v1)
{
    __shared__ float sm[68][SMC];
    const int b = blockIdx.y;
    const int e = g_idx[b];
    if (e == 2) return;
    const int c = blockIdx.x;

    const float gg = (e == 0 ? g0[c] : g1[c]);
    const float vv = (e == 0 ? v0[c] : v1[c]);
    const float mm = (e == 0 ? m0[c] : m1[c]);
    const float bb = (e == 0 ? b0[c] : b1[c]);
    const float scale = gg * rsqrtf(vv + EPSV);
    const float* kw = (e == 0 ? k0 : k1) + c * 9;
    const float* xp = x + ((size_t)b*NC + c) * NHW;
    __half* outp = g_feat16 + ((size_t)b*NC + c) * NHW;

    if (e == 0) dwconv_plane<1>(sm, xp, kw, scale, mm, bb, outp);
    else        dwconv_plane<2>(sm, xp, kw, scale, mm, bb, outp);
}

// ---------------------------------------------------------------------------
// fp16 tensor-core primitives
// ---------------------------------------------------------------------------
__device__ __forceinline__ void ldsm4(uint32_t r[4], uint32_t a) {
    asm volatile("ldmatrix.sync.aligned.m8n8.x4.shared.b16 {%0,%1,%2,%3}, [%4];"
        : "=r"(r[0]), "=r"(r[1]), "=r"(r[2]), "=r"(r[3]) : "r"(a));
}
__device__ __forceinline__ void ldsm4t(uint32_t r[4], uint32_t a) {
    asm volatile("ldmatrix.sync.aligned.m8n8.x4.trans.shared.b16 {%0,%1,%2,%3}, [%4];"
        : "=r"(r[0]), "=r"(r[1]), "=r"(r[2]), "=r"(r[3]) : "r"(a));
}
__device__ __forceinline__ void mma16816(float c[4], const uint32_t a[4],
                                         uint32_t b0, uint32_t b1) {
    asm volatile(
        "mma.sync.aligned.m16n8k16.row.col.f32.f16.f16.f32 "
        "{%0,%1,%2,%3}, {%4,%5,%6,%7}, {%8,%9}, {%0,%1,%2,%3};"
        : "+f"(c[0]), "+f"(c[1]), "+f"(c[2]), "+f"(c[3])
        : "r"(a[0]), "r"(a[1]), "r"(a[2]), "r"(a[3]), "r"(b0), "r"(b1));
}

// A chunk: 128 m x 32 k half, row padded to 80 B  -> conflict-free LDSM (5m+u mod 8)
// B stage: 32 k x 128 n half, row padded to 272 B -> conflict-free LDSM (k+u mod 8)
#define A_CHUNK 10240
#define B_STAGE 8704

// ---------------------------------------------------------------------------
// fp16 pipelined GEMM core: C(128x128) = A(128x256) @ B(256x128), BK=32,
// 8 chunks; B via cp.async 3 stages (distance 2); A double-buffered (LDG+STS).
// Fills acc[mt][nt][4] in the standard m16n8 fragment layout.
// ---------------------------------------------------------------------------
__device__ __forceinline__ void hgemm_pipe(
    char* AsPtr, char* BsPtr,
    const __half* __restrict__ A, const __half* __restrict__ Bm,
    int m0, int n0, float acc[2][8][4])
{
    const int tid  = threadIdx.x;
    const int lane = tid & 31;
    const int wid  = tid >> 5;
    const int wm   = wid & 3;
    const int wn   = wid >> 2;
    const int grp  = lane >> 3;
    const int lr   = lane & 7;

    const uint32_t asU = smem_addr_u32(AsPtr);
    const uint32_t bsU = smem_addr_u32(BsPtr);

    // staging maps (2 x 16B per thread per chunk, each operand)
    const int am0 = tid >> 2,        au0 = tid & 3;          // ids tid
    const int am1 = (tid+256) >> 2,  au1 = tid & 3;          // ids tid+256
    const __half* aSrc0 = A + (size_t)(m0 + am0) * NC + au0*8;
    const __half* aSrc1 = A + (size_t)(m0 + am1) * NC + au1*8;
    char* aDst0 = AsPtr + am0*80 + au0*16;
    char* aDst1 = AsPtr + am1*80 + au1*16;

    const int bk = tid >> 4, bu = tid & 15;
    const __half* bSrc0 = Bm + (size_t)bk * NHW + n0 + bu*8;         // k row bk
    const uint32_t bD0 = bsU + bk*272 + bu*16;
    const uint32_t bD1 = bsU + (bk+16)*272 + bu*16;                  // k row bk+16

    // fragment byte offsets (within a chunk/stage)
    const uint32_t aFrag = (uint32_t)((wm*32 + (grp&1)*8 + lr)*80 + (grp>>1)*16);
    const uint32_t bFrag = (uint32_t)(((grp&1)*8 + lr)*272 + wn*128 + (grp>>1)*16);

    // ---- prologue: B(0)->s0, B(1)->s1 ; A(0) -> buf0 ----
    cp_async16(bD0, bSrc0);
    cp_async16(bD1, bSrc0 + (size_t)16*NHW);
    CP_COMMIT();
    cp_async16(bD0 + B_STAGE, bSrc0 + (size_t)32*NHW);
    cp_async16(bD1 + B_STAGE, bSrc0 + (size_t)48*NHW);
    CP_COMMIT();
    {
        uint4 v0 = *reinterpret_cast<const uint4*>(aSrc0);
        uint4 v1 = *reinterpret_cast<const uint4*>(aSrc1);
        *reinterpret_cast<uint4*>(aDst0) = v0;
        *reinterpret_cast<uint4*>(aDst1) = v1;
    }
    CP_WAIT(1);
    __syncthreads();

    int bufA = 0;
    #pragma unroll 1
    for (int kc = 0; kc < 8; kc++) {
        const uint32_t bsStage = bsU + (uint32_t)(kc % 3) * B_STAGE;

        if (kc + 2 < 8) {
            const uint32_t so = (uint32_t)((kc + 2) % 3) * B_STAGE;
            const __half* s = bSrc0 + (size_t)(kc + 2) * 32 * NHW;
            cp_async16(bD0 + so, s);
            cp_async16(bD1 + so, s + (size_t)16*NHW);
            CP_COMMIT();
        }
        uint4 av0, av1;
        const bool has_next = (kc + 1) < 8;
        if (has_next) {
            av0 = *reinterpret_cast<const uint4*>(aSrc0 + (kc+1)*32);
            av1 = *reinterpret_cast<const uint4*>(aSrc1 + (kc+1)*32);
        }

        // ---- compute chunk kc ----
        const uint32_t asCur = asU + (uint32_t)bufA * A_CHUNK;
        #pragma unroll
        for (int ks = 0; ks < 2; ks++) {
            uint32_t a0[4], a1[4];
            ldsm4(a0, asCur + aFrag + ks*32);
            ldsm4(a1, asCur + aFrag + 1280 + ks*32);
            uint32_t b[4][4];
            #pragma unroll
            for (int j = 0; j < 4; j++)
                ldsm4t(b[j], bsStage + bFrag + ks*4352 + j*32);
            #pragma unroll
            for (int nt = 0; nt < 8; nt++) {
                const uint32_t b0 = b[nt>>1][(nt&1)*2];
                const uint32_t b1 = b[nt>>1][(nt&1)*2 + 1];
                mma16816(acc[0][nt], a0, b0, b1);
                mma16816(acc[1][nt], a1, b0, b1);
            }
        }

        if (has_next) {
            char* base = AsPtr + (bufA ^ 1) * A_CHUNK;
            *reinterpret_cast<uint4*>(base + am0*80 + au0*16) = av0;
            *reinterpret_cast<uint4*>(base + am1*80 + au1*16) = av1;
            bufA ^= 1;
        }

        if (kc + 2 < 8) { CP_WAIT(1); } else { CP_WAIT(0); }
        __syncthreads();
    }
}

// ---------------------------------------------------------------------------
// 3b) feat GEMM: feat[b] = bn_gelu(e2_k @ x16[b]) for idx==2, fp16 out
// ---------------------------------------------------------------------------
__global__ void __launch_bounds__(256, 2) feat_gemm_kernel(
    const float* __restrict__ p0, const float* __restrict__ p1,
    const float* __restrict__ p2, const float* __restrict__ p3)
{
    __shared__ __align__(16) char As[2*A_CHUNK];
    __shared__ __align__(16) char Bs[3*B_STAGE];

    const int bz = blockIdx.z;
    if (g_idx[bz] != 2) return;
    const int m0 = blockIdx.y * 128;
    const int n0 = blockIdx.x * 128;

    float acc[2][8][4];
    #pragma unroll
    for (int i = 0; i < 2; i++)
        #pragma unroll
        for (int j = 0; j < 8; j++)
            #pragma unroll
            for (int t = 0; t < 4; t++) acc[i][j][t] = 0.f;

    hgemm_pipe(As, Bs, g_wt16[3], g_x16 + (size_t)bz*NCHW, m0, n0, acc);

    const int lane = threadIdx.x & 31;
    const int wid  = threadIdx.x >> 5;
    const int wm   = wid & 3;
    const int wn   = wid >> 2;
    const int gID  = lane >> 2;
    const int qid  = lane & 3;
    __half* Cm = g_feat16 + (size_t)bz*NCHW;

    #pragma unroll
    for (int mt = 0; mt < 2; mt++) {
        #pragma unroll
        for (int half = 0; half < 2; half++) {
            const int o = m0 + wm*32 + mt*16 + half*8 + gID;
            float sc = p0[o] * rsqrtf(p3[o] + EPSV);
            float mm = p2[o];
            float bb = p1[o];
            __half* cp = Cm + (size_t)o * NHW + n0 + wn*64 + qid*2;
            #pragma unroll
            for (int nt = 0; nt < 8; nt++) {
                float z0 = acc[mt][nt][half*2 + 0];
                float z1 = acc[mt][nt][half*2 + 1];
                z0 = (z0 - mm) * sc + bb; z0 = gelu_exact(z0);
                z1 = (z1 - mm) * sc + bb; z1 = gelu_exact(z1);
                *reinterpret_cast<__half2*>(cp + nt*8) = __floats2half2_rn(z0, z1);
            }
        }
    }
}

// ---------------------------------------------------------------------------
// 4) out GEMM: out[b] = e{idx}_pw @ feat16[b] + e{idx}_pb (fp32 out)
// ---------------------------------------------------------------------------
__global__ void __launch_bounds__(256, 2) out_gemm_kernel(
    const float* __restrict__ pb0, const float* __restrict__ pb1,
    const float* __restrict__ pb2, float* __restrict__ out)
{
    __shared__ __align__(16) char As[2*A_CHUNK];
    __shared__ __align__(16) char Bs[3*B_STAGE];

    const int bz = blockIdx.z;
    const int e  = g_idx[bz];
    const float* pb = (e == 0) ? pb0 : (e == 1 ? pb1 : pb2);
    const int m0 = blockIdx.y * 128;
    const int n0 = blockIdx.x * 128;

    float acc[2][8][4];
    #pragma unroll
    for (int i = 0; i < 2; i++)
        #pragma unroll
        for (int j = 0; j < 8; j++)
            #pragma unroll
            for (int t = 0; t < 4; t++) acc[i][j][t] = 0.f;

    hgemm_pipe(As, Bs, g_wt16[e], g_feat16 + (size_t)bz*NCHW, m0, n0, acc);

    const int lane = threadIdx.x & 31;
    const int wid  = threadIdx.x >> 5;
    const int wm   = wid & 3;
    const int wn   = wid >> 2;
    const int gID  = lane >> 2;
    const int qid  = lane & 3;
    float* Cm = out + (size_t)bz*NCHW;

    #pragma unroll
    for (int mt = 0; mt < 2; mt++) {
        #pragma unroll
        for (int half = 0; half < 2; half++) {
            const int o = m0 + wm*32 + mt*16 + half*8 + gID;
            const float bb = pb[o];
            float* cp = Cm + (size_t)o * NHW + n0 + wn*64 + qid*2;
            #pragma unroll
            for (int nt = 0; nt < 8; nt++) {
                *reinterpret_cast<float2*>(cp + nt*8) =
                    make_float2(acc[mt][nt][half*2 + 0] + bb,
                                acc[mt][nt][half*2 + 1] + bb);
            }
        }
    }
}

// ---------------------------------------------------------------------------
extern "C" void kernel_launch(void* const* d_in, const int* in_sizes, int n_in,
                              void* d_out, int out_size) {
    const float* x    = (const float*)d_in[0];
    const float* rw   = (const float*)d_in[1];
    const float* rb   = (const float*)d_in[2];
    const float* e0_k = (const float*)d_in[3];
    const float* e0_g = (const float*)d_in[4];
    const float* e0_b = (const float*)d_in[5];
    const float* e0_m = (const float*)d_in[6];
    const float* e0_v = (const float*)d_in[7];
    const float* e0_pw= (const float*)d_in[8];
    const float* e0_pb= (const float*)d_in[9];
    const float* e1_k = (const float*)d_in[10];
    const float* e1_g = (const float*)d_in[11];
    const float* e1_b = (const float*)d_in[12];
    const float* e1_m = (const float*)d_in[13];
    const float* e1_v = (const float*)d_in[14];
    const float* e1_pw= (const float*)d_in[15];
    const float* e1_pb= (const float*)d_in[16];
    const float* e2_k = (const float*)d_in[17];
    const float* e2_g = (const float*)d_in[18];
    const float* e2_b = (const float*)d_in[19];
    const float* e2_m = (const float*)d_in[20];
    const float* e2_v = (const float*)d_in[21];
    const float* e2_pw= (const float*)d_in[22];
    const float* e2_pb= (const float*)d_in[23];
    float* out = (float*)d_out;

    pool_prep_kernel<<<NB*NC + 1024, 256>>>(x, e0_pw, e1_pw, e2_pw, e2_k);
    route_kernel<<<1, 32>>>(rw, rb);

    dwconv_bn_gelu_kernel<<<dim3(NC, NB), 256>>>(
        x, e0_k, e0_g, e0_b, e0_m, e0_v,
           e1_k, e1_g, e1_b, e1_m, e1_v);

    dim3 ggrid(NHW/128, NC/128, NB);   // (32, 2, 32)
    feat_gemm_kernel<<<ggrid, 256>>>(e2_g, e2_b, e2_m, e2_v);
    out_gemm_kernel<<<ggrid, 256>>>(e0_pb, e1_pb, e2_pb, out);
}

// round 15
// speedup vs baseline: 1.8115x; 1.0255x over previous
#include <cuda_runtime.h>
#include <cuda_fp16.h>
#include <math.h>
#include <stdint.h>

#define NB 32
#define NC 256
#define NH 64
#define NW 64
#define NHW 4096
#define NCHW (NC*NHW)
#define EPSV 1e-5f

// Scratch (allocation-free rule: __device__ globals)
__device__ float  g_pooled[NB*NC];
__device__ int    g_idx[NB];
__device__ __half g_x16[(size_t)NB*NCHW];     // fp16 copy of x (written by pool)
__device__ __half g_feat16[(size_t)NB*NCHW];  // fp16 feature scratch, natural [c][n]
__device__ __half g_wt16[4][NC*NC];           // fp16 weights: e0_pw,e1_pw,e2_pw,e2_k

__device__ __forceinline__ float gelu_exact(float z) {
    return 0.5f * z * (1.0f + erff(z * 0.7071067811865475f));
}
__device__ __forceinline__ uint32_t smem_addr_u32(const void* p) {
    return (uint32_t)__cvta_generic_to_shared(p);
}
__device__ __forceinline__ void cp_async16(uint32_t dst, const void* src) {
    asm volatile("cp.async.ca.shared.global [%0], [%1], 16;" :: "r"(dst), "l"(src));
}
#define CP_COMMIT() asm volatile("cp.async.commit_group;")
#define CP_WAIT(n)  asm volatile("cp.async.wait_group %0;" :: "n"(n))

__device__ __forceinline__ uint32_t h2u(__half2 h) {
    return *reinterpret_cast<uint32_t*>(&h);
}

// ---------------------------------------------------------------------------
// 1) Fused: global average pool (+ fp16 copy of x) + weight pre-convert
// ---------------------------------------------------------------------------
__global__ void pool_prep_kernel(const float* __restrict__ x,
                                 const float* __restrict__ w0, const float* __restrict__ w1,
                                 const float* __restrict__ w2, const float* __restrict__ k2) {
    if (blockIdx.x < NB*NC) {
        int bc = blockIdx.x;
        const float4* p = reinterpret_cast<const float4*>(x + (size_t)bc * NHW);
        uint2* o16 = reinterpret_cast<uint2*>(g_x16 + (size_t)bc * NHW);
        float s = 0.f;
        for (int i = threadIdx.x; i < NHW/4; i += 256) {
            float4 v = p[i];
            s += (v.x + v.y) + (v.z + v.w);
            o16[i] = make_uint2(h2u(__floats2half2_rn(v.x, v.y)),
                                h2u(__floats2half2_rn(v.z, v.w)));
        }
        __shared__ float red[8];
        #pragma unroll
        for (int o = 16; o > 0; o >>= 1) s += __shfl_down_sync(0xffffffffu, s, o);
        if ((threadIdx.x & 31) == 0) red[threadIdx.x >> 5] = s;
        __syncthreads();
        if (threadIdx.x < 8) {
            float t = red[threadIdx.x];
            #pragma unroll
            for (int o = 4; o > 0; o >>= 1) t += __shfl_down_sync(0xffu, t, o);
            if (threadIdx.x == 0) g_pooled[bc] = t * (1.0f / NHW);
        }
    } else {
        int i = (blockIdx.x - NB*NC) * 256 + threadIdx.x;
        int m = i >> 16;
        int o = i & 0xFFFF;
        const float* src = (m == 0) ? w0 : (m == 1) ? w1 : (m == 2) ? w2 : k2;
        g_wt16[m][o] = __float2half_rn(src[o]);
    }
}

// ---------------------------------------------------------------------------
// 2) Router
// ---------------------------------------------------------------------------
__global__ void route_kernel(const float* __restrict__ rw, const float* __restrict__ rb) {
    int b = threadIdx.x;
    if (b >= NB) return;
    float best = -1e30f; int bi = 0;
    #pragma unroll
    for (int j = 0; j < 3; j++) {
        float s = rb[j];
        const float* w = rw + j*NC;
        const float* p = g_pooled + b*NC;
        for (int c = 0; c < NC; c++) s = fmaf(p[c], w[c], s);
        if (s > best) { best = s; bi = j; }
    }
    g_idx[b] = bi;
}

// ---------------------------------------------------------------------------
// 3a) Depthwise 3x3 conv + BN + exact GELU (R9-proven); output fp16 natural
// ---------------------------------------------------------------------------
#define SMC 70

template<int D>
__device__ __forceinline__ void dwconv_plane(
    float (*sm)[SMC], const float* __restrict__ xp, const float* __restrict__ kw9,
    float scale, float mm, float bb, __half* __restrict__ outp)
{
    const int tid = threadIdx.x;

    for (int i = tid; i < 272; i += 256) {
        int r = i / 68, c = i % 68;
        sm[(r < 2) ? r : r + 64][c] = 0.f;
    }
    {
        int r = 2 + (tid >> 2);
        int c = tid & 3;
        sm[r][(c < 2) ? c : c + 64] = 0.f;
    }

    #pragma unroll
    for (int i = 0; i < 4; i++) {
        int idx = tid + i*256;
        int y = idx >> 4, x4 = (idx & 15) * 4;
        float4 v = reinterpret_cast<const float4*>(xp)[idx];
        sm[y+2][x4+2+0] = v.x;
        sm[y+2][x4+2+1] = v.y;
        sm[y+2][x4+2+2] = v.z;
        sm[y+2][x4+2+3] = v.w;
    }
    __syncthreads();

    const int y  = tid >> 2;
    const int x0 = (tid & 3) * 16;

    float acc[16];
    #pragma unroll
    for (int j = 0; j < 16; j++) acc[j] = 0.f;

    #pragma unroll
    for (int dy = 0; dy < 3; dy++) {
        const float* row = &sm[y + 2 + (dy-1)*D][x0 + 2 - D];
        const float w0 = kw9[dy*3 + 0];
        const float w1 = kw9[dy*3 + 1];
        const float w2 = kw9[dy*3 + 2];
        float v[16 + 2*D];
        #pragma unroll
        for (int j = 0; j < 16 + 2*D; j++) v[j] = row[j];
        #pragma unroll
        for (int j = 0; j < 16; j++)
            acc[j] = fmaf(w0, v[j], fmaf(w1, v[j+D], fmaf(w2, v[j+2*D], acc[j])));
    }

    uint32_t pk[8];
    #pragma unroll
    for (int jj = 0; jj < 8; jj++) {
        float z0 = (acc[2*jj]   - mm) * scale + bb;
        float z1 = (acc[2*jj+1] - mm) * scale + bb;
        pk[jj] = h2u(__floats2half2_rn(gelu_exact(z0), gelu_exact(z1)));
    }
    __half* op = outp + y*NW + x0;
    *reinterpret_cast<uint4*>(op)     = make_uint4(pk[0], pk[1], pk[2], pk[3]);
    *reinterpret_cast<uint4*>(op + 8) = make_uint4(pk[4], pk[5], pk[6], pk[7]);
}

__global__ void __launch_bounds__(256) dwconv_bn_gelu_kernel(
    const float* __restrict__ x,
    const float* __restrict__ k0, const float* __restrict__ g0, const float* __restrict__ b0,
    const float* __restrict__ m0, const float* __restrict__ v0,
    const float* __restrict__ k1, const float* __restrict__ g1, const float* __restrict__ b1,
    const float* __restrict__ m1, const float* __restrict__ v1)
{
    __shared__ float sm[68][SMC];
    const int b = blockIdx.y;
    const int e = g_idx[b];
    if (e == 2) return;
    const int c = blockIdx.x;

    const float gg = (e == 0 ? g0[c] : g1[c]);
    const float vv = (e == 0 ? v0[c] : v1[c]);
    const float mm = (e == 0 ? m0[c] : m1[c]);
    const float bb = (e == 0 ? b0[c] : b1[c]);
    const float scale = gg * rsqrtf(vv + EPSV);
    const float* kw = (e == 0 ? k0 : k1) + c * 9;
    const float* xp = x + ((size_t)b*NC + c) * NHW;
    __half* outp = g_feat16 + ((size_t)b*NC + c) * NHW;

    if (e == 0) dwconv_plane<1>(sm, xp, kw, scale, mm, bb, outp);
    else        dwconv_plane<2>(sm, xp, kw, scale, mm, bb, outp);
}

// ---------------------------------------------------------------------------
// fp16 tensor-core primitives
// ---------------------------------------------------------------------------
__device__ __forceinline__ void ldsm4(uint32_t r[4], uint32_t a) {
    asm volatile("ldmatrix.sync.aligned.m8n8.x4.shared.b16 {%0,%1,%2,%3}, [%4];"
        : "=r"(r[0]), "=r"(r[1]), "=r"(r[2]), "=r"(r[3]) : "r"(a));
}
__device__ __forceinline__ void ldsm4t(uint32_t r[4], uint32_t a) {
    asm volatile("ldmatrix.sync.aligned.m8n8.x4.trans.shared.b16 {%0,%1,%2,%3}, [%4];"
        : "=r"(r[0]), "=r"(r[1]), "=r"(r[2]), "=r"(r[3]) : "r"(a));
}
__device__ __forceinline__ void mma16816(float c[4], const uint32_t a[4],
                                         uint32_t b0, uint32_t b1) {
    asm volatile(
        "mma.sync.aligned.m16n8k16.row.col.f32.f16.f16.f32 "
        "{%0,%1,%2,%3}, {%4,%5,%6,%7}, {%8,%9}, {%0,%1,%2,%3};"
        : "+f"(c[0]), "+f"(c[1]), "+f"(c[2]), "+f"(c[3])
        : "r"(a[0]), "r"(a[1]), "r"(a[2]), "r"(a[3]), "r"(b0), "r"(b1));
}

#define A_CHUNK 10240
#define B_STAGE 8704

// ---------------------------------------------------------------------------
// fp16 pipelined GEMM core (R14-proven)
// ---------------------------------------------------------------------------
__device__ __forceinline__ void hgemm_pipe(
    char* AsPtr, char* BsPtr,
    const __half* __restrict__ A, const __half* __restrict__ Bm,
    int m0, int n0, float acc[2][8][4])
{
    const int tid  = threadIdx.x;
    const int lane = tid & 31;
    const int wid  = tid >> 5;
    const int wm   = wid & 3;
    const int wn   = wid >> 2;
    const int grp  = lane >> 3;
    const int lr   = lane & 7;

    const uint32_t asU = smem_addr_u32(AsPtr);
    const uint32_t bsU = smem_addr_u32(BsPtr);

    const int am0 = tid >> 2,        au0 = tid & 3;
    const int am1 = (tid+256) >> 2,  au1 = tid & 3;
    const __half* aSrc0 = A + (size_t)(m0 + am0) * NC + au0*8;
    const __half* aSrc1 = A + (size_t)(m0 + am1) * NC + au1*8;
    char* aDst0 = AsPtr + am0*80 + au0*16;
    char* aDst1 = AsPtr + am1*80 + au1*16;

    const int bk = tid >> 4, bu = tid & 15;
    const __half* bSrc0 = Bm + (size_t)bk * NHW + n0 + bu*8;
    const uint32_t bD0 = bsU + bk*272 + bu*16;
    const uint32_t bD1 = bsU + (bk+16)*272 + bu*16;

    const uint32_t aFrag = (uint32_t)((wm*32 + (grp&1)*8 + lr)*80 + (grp>>1)*16);
    const uint32_t bFrag = (uint32_t)(((grp&1)*8 + lr)*272 + wn*128 + (grp>>1)*16);

    cp_async16(bD0, bSrc0);
    cp_async16(bD1, bSrc0 + (size_t)16*NHW);
    CP_COMMIT();
    cp_async16(bD0 + B_STAGE, bSrc0 + (size_t)32*NHW);
    cp_async16(bD1 + B_STAGE, bSrc0 + (size_t)48*NHW);
    CP_COMMIT();
    {
        uint4 v0 = *reinterpret_cast<const uint4*>(aSrc0);
        uint4 v1 = *reinterpret_cast<const uint4*>(aSrc1);
        *reinterpret_cast<uint4*>(aDst0) = v0;
        *reinterpret_cast<uint4*>(aDst1) = v1;
    }
    CP_WAIT(1);
    __syncthreads();

    int bufA = 0;
    #pragma unroll 1
    for (int kc = 0; kc < 8; kc++) {
        const uint32_t bsStage = bsU + (uint32_t)(kc % 3) * B_STAGE;

        if (kc + 2 < 8) {
            const uint32_t so = (uint32_t)((kc + 2) % 3) * B_STAGE;
            const __half* s = bSrc0 + (size_t)(kc + 2) * 32 * NHW;
            cp_async16(bD0 + so, s);
            cp_async16(bD1 + so, s + (size_t)16*NHW);
            CP_COMMIT();
        }
        uint4 av0, av1;
        const bool has_next = (kc + 1) < 8;
        if (has_next) {
            av0 = *reinterpret_cast<const uint4*>(aSrc0 + (kc+1)*32);
            av1 = *reinterpret_cast<const uint4*>(aSrc1 + (kc+1)*32);
        }

        const uint32_t asCur = asU + (uint32_t)bufA * A_CHUNK;
        #pragma unroll
        for (int ks = 0; ks < 2; ks++) {
            uint32_t a0[4], a1[4];
            ldsm4(a0, asCur + aFrag + ks*32);
            ldsm4(a1, asCur + aFrag + 1280 + ks*32);
            uint32_t b[4][4];
            #pragma unroll
            for (int j = 0; j < 4; j++)
                ldsm4t(b[j], bsStage + bFrag + ks*4352 + j*32);
            #pragma unroll
            for (int nt = 0; nt < 8; nt++) {
                const uint32_t b0 = b[nt>>1][(nt&1)*2];
                const uint32_t b1 = b[nt>>1][(nt&1)*2 + 1];
                mma16816(acc[0][nt], a0, b0, b1);
                mma16816(acc[1][nt], a1, b0, b1);
            }
        }

        if (has_next) {
            char* base = AsPtr + (bufA ^ 1) * A_CHUNK;
            *reinterpret_cast<uint4*>(base + am0*80 + au0*16) = av0;
            *reinterpret_cast<uint4*>(base + am1*80 + au1*16) = av1;
            bufA ^= 1;
        }

        if (kc + 2 < 8) { CP_WAIT(1); } else { CP_WAIT(0); }
        __syncthreads();
    }
}

// ---------------------------------------------------------------------------
// 3b) feat GEMM: feat[b] = bn_gelu(e2_k @ x16[b]) for idx==2, fp16 out
// ---------------------------------------------------------------------------
__global__ void __launch_bounds__(256, 2) feat_gemm_kernel(
    const float* __restrict__ p0, const float* __restrict__ p1,
    const float* __restrict__ p2, const float* __restrict__ p3)
{
    __shared__ __align__(16) char As[2*A_CHUNK];
    __shared__ __align__(16) char Bs[3*B_STAGE];

    const int bz = blockIdx.z;
    if (g_idx[bz] != 2) return;
    const int m0 = blockIdx.y * 128;
    const int n0 = blockIdx.x * 128;

    float acc[2][8][4];
    #pragma unroll
    for (int i = 0; i < 2; i++)
        #pragma unroll
        for (int j = 0; j < 8; j++)
            #pragma unroll
            for (int t = 0; t < 4; t++) acc[i][j][t] = 0.f;

    hgemm_pipe(As, Bs, g_wt16[3], g_x16 + (size_t)bz*NCHW, m0, n0, acc);

    const int lane = threadIdx.x & 31;
    const int wid  = threadIdx.x >> 5;
    const int wm   = wid & 3;
    const int wn   = wid >> 2;
    const int gID  = lane >> 2;
    const int qid  = lane & 3;
    __half* Cm = g_feat16 + (size_t)bz*NCHW;

    #pragma unroll
    for (int mt = 0; mt < 2; mt++) {
        #pragma unroll
        for (int half = 0; half < 2; half++) {
            const int o = m0 + wm*32 + mt*16 + half*8 + gID;
            float sc = p0[o] * rsqrtf(p3[o] + EPSV);
            float mm = p2[o];
            float bb = p1[o];
            __half* cp = Cm + (size_t)o * NHW + n0 + wn*64 + qid*2;
            #pragma unroll
            for (int nt = 0; nt < 8; nt++) {
                float z0 = acc[mt][nt][half*2 + 0];
                float z1 = acc[mt][nt][half*2 + 1];
                z0 = (z0 - mm) * sc + bb; z0 = gelu_exact(z0);
                z1 = (z1 - mm) * sc + bb; z1 = gelu_exact(z1);
                *reinterpret_cast<__half2*>(cp + nt*8) = __floats2half2_rn(z0, z1);
            }
        }
    }
}

// ---------------------------------------------------------------------------
// 4) out GEMM: out[b] = e{idx}_pw @ feat16[b] + e{idx}_pb (fp32 out)
// ---------------------------------------------------------------------------
__global__ void __launch_bounds__(256, 2) out_gemm_kernel(
    const float* __restrict__ pb0, const float* __restrict__ pb1,
    const float* __restrict__ pb2, float* __restrict__ out)
{
    __shared__ __align__(16) char As[2*A_CHUNK];
    __shared__ __align__(16) char Bs[3*B_STAGE];

    const int bz = blockIdx.z;
    const int e  = g_idx[bz];
    const float* pb = (e == 0) ? pb0 : (e == 1 ? pb1 : pb2);
    const int m0 = blockIdx.y * 128;
    const int n0 = blockIdx.x * 128;

    float acc[2][8][4];
    #pragma unroll
    for (int i = 0; i < 2; i++)
        #pragma unroll
        for (int j = 0; j < 8; j++)
            #pragma unroll
            for (int t = 0; t < 4; t++) acc[i][j][t] = 0.f;

    hgemm_pipe(As, Bs, g_wt16[e], g_feat16 + (size_t)bz*NCHW, m0, n0, acc);

    const int lane = threadIdx.x & 31;
    const int wid  = threadIdx.x >> 5;
    const int wm   = wid & 3;
    const int wn   = wid >> 2;
    const int gID  = lane >> 2;
    const int qid  = lane & 3;
    float* Cm = out + (size_t)bz*NCHW;

    #pragma unroll
    for (int mt = 0; mt < 2; mt++) {
        #pragma unroll
        for (int half = 0; half < 2; half++) {
            const int o = m0 + wm*32 + mt*16 + half*8 + gID;
            const float bb = pb[o];
            float* cp = Cm + (size_t)o * NHW + n0 + wn*64 + qid*2;
            #pragma unroll
            for (int nt = 0; nt < 8; nt++) {
                *reinterpret_cast<float2*>(cp + nt*8) =
                    make_float2(acc[mt][nt][half*2 + 0] + bb,
                                acc[mt][nt][half*2 + 1] + bb);
            }
        }
    }
}

// ---------------------------------------------------------------------------
// Launch: graph fork-join — dwconv (main stream) runs CONCURRENTLY with
// feat_gemm (side stream); both join before out_gemm. Streams/events are
// host objects created once via static init (no device memory involved).
// ---------------------------------------------------------------------------
static cudaStream_t get_side_stream() {
    static cudaStream_t s = [](){
        cudaStream_t t;
        cudaStreamCreateWithFlags(&t, cudaStreamNonBlocking);
        return t;
    }();
    return s;
}
static cudaEvent_t get_event(int i) {
    static cudaEvent_t e[2] = { [](){
        cudaEvent_t t; cudaEventCreateWithFlags(&t, cudaEventDisableTiming); return t; }(),
        [](){
        cudaEvent_t t; cudaEventCreateWithFlags(&t, cudaEventDisableTiming); return t; }() };
    return e[i];
}

extern "C" void kernel_launch(void* const* d_in, const int* in_sizes, int n_in,
                              void* d_out, int out_size) {
    const float* x    = (const float*)d_in[0];
    const float* rw   = (const float*)d_in[1];
    const float* rb   = (const float*)d_in[2];
    const float* e0_k = (const float*)d_in[3];
    const float* e0_g = (const float*)d_in[4];
    const float* e0_b = (const float*)d_in[5];
    const float* e0_m = (const float*)d_in[6];
    const float* e0_v = (const float*)d_in[7];
    const float* e0_pw= (const float*)d_in[8];
    const float* e0_pb= (const float*)d_in[9];
    const float* e1_k = (const float*)d_in[10];
    const float* e1_g = (const float*)d_in[11];
    const float* e1_b = (const float*)d_in[12];
    const float* e1_m = (const float*)d_in[13];
    const float* e1_v = (const float*)d_in[14];
    const float* e1_pw= (const float*)d_in[15];
    const float* e1_pb= (const float*)d_in[16];
    const float* e2_k = (const float*)d_in[17];
    const float* e2_g = (const float*)d_in[18];
    const float* e2_b = (const float*)d_in[19];
    const float* e2_m = (const float*)d_in[20];
    const float* e2_v = (const float*)d_in[21];
    const float* e2_pw= (const float*)d_in[22];
    const float* e2_pb= (const float*)d_in[23];
    float* out = (float*)d_out;

    cudaStream_t s1 = get_side_stream();
    cudaEvent_t evFork = get_event(0);
    cudaEvent_t evJoin = get_event(1);

    pool_prep_kernel<<<NB*NC + 1024, 256>>>(x, e0_pw, e1_pw, e2_pw, e2_k);
    route_kernel<<<1, 32>>>(rw, rb);

    // fork: side stream waits for route, runs feat_gemm concurrently w/ dwconv
    cudaEventRecord(evFork, 0);
    cudaStreamWaitEvent(s1, evFork, 0);

    dim3 ggrid(NHW/128, NC/128, NB);   // (32, 2, 32)
    feat_gemm_kernel<<<ggrid, 256, 0, s1>>>(e2_g, e2_b, e2_m, e2_v);

    dwconv_bn_gelu_kernel<<<dim3(NC, NB), 256>>>(
        x, e0_k, e0_g, e0_b, e0_m, e0_v,
           e1_k, e1_g, e1_b, e1_m, e1_v);

    // join: main stream waits for feat_gemm before out_gemm
    cudaEventRecord(evJoin, s1);
    cudaStreamWaitEvent(0, evJoin, 0);

    out_gemm_kernel<<<ggrid, 256>>>(e0_pb, e1_pb, e2_pb, out);
}